// round 3
// baseline (speedup 1.0000x reference)
#include <cuda_runtime.h>
#include <math.h>

#define BN 256
#define SN 256
#define EN 300
#define HN 300
#define G4 1200
#define DN 601
#define AN 16
#define POLN 3

// ---------------- static device scratch (no allocations allowed) ----------------
__device__ float d_wihT[2][300 * 1200];      // input weights, k-major
__device__ float d_whhT[2][300 * 1200];      // recurrent weights, k-major
__device__ float d_gwihT[601 * 900];         // GRU W_ih^T  (k-major)
__device__ float d_gwhhT[300 * 900];         // GRU W_hh^T  (k-major)
__device__ float d_Gpre[2 * 65536 * 1200];   // input gates, layout [dir][t][n][b]
__device__ float d_mem[65536 * 601];         // location-weighted memory [b][s][d]
__device__ float d_hstate[2][2][300 * 256];  // [dir][parity][u][b]
__device__ float d_cstate[2][300 * 256];     // [dir][u][b]
__device__ float d_gmT[65536];               // [s][b]  mem-part of attention logit
__device__ float d_alphaT[65536];            // [s][b]
__device__ float d_gofs[256];
__device__ float d_asp[256 * 300];
__device__ float d_casp[256];
__device__ float d_et[256 * 300];
__device__ float d_ivec[256 * 601];
__device__ float d_llen[256], d_alen[256], d_mlen[256];

__device__ __forceinline__ float sigf(float x) { return 1.f / (1.f + expf(-x)); }

// ---------------- weight transposes ----------------
__global__ void k_transpose_all(const float* __restrict__ fwih, const float* __restrict__ fwhh,
                                const float* __restrict__ bwih, const float* __restrict__ bwhh,
                                const float* __restrict__ gwih, const float* __restrict__ gwhh) {
    int id = blockIdx.z;
    const float* src;
    float* dst;
    int R, C;
    switch (id) {
        case 0: src = fwih; dst = d_wihT[0]; R = 1200; C = 300; break;
        case 1: src = fwhh; dst = d_whhT[0]; R = 1200; C = 300; break;
        case 2: src = bwih; dst = d_wihT[1]; R = 1200; C = 300; break;
        case 3: src = bwhh; dst = d_whhT[1]; R = 1200; C = 300; break;
        case 4: src = gwih; dst = d_gwihT;   R = 900;  C = 601; break;
        default: src = gwhh; dst = d_gwhhT;  R = 900;  C = 300; break;
    }
    __shared__ float tile[32][33];
    int c0 = blockIdx.x * 32, r0 = blockIdx.y * 32;
    int x = threadIdx.x, y = threadIdx.y;  // 32 x 8
    #pragma unroll
    for (int i = 0; i < 32; i += 8) {
        int r = r0 + y + i, c = c0 + x;
        if (r < R && c < C) tile[y + i][x] = src[(size_t)r * C + c];
    }
    __syncthreads();
    #pragma unroll
    for (int i = 0; i < 32; i += 8) {
        int c = c0 + y + i, r = r0 + x;
        if (c < C && r < R) dst[(size_t)c * R + r] = tile[x][y + i];
    }
}

// ---------------- lengths / aspect vector / init ----------------
__global__ void k_prep_b(const int* __restrict__ text, const int* __restrict__ left,
                         const int* __restrict__ aspect, const float* __restrict__ embed,
                         const float* __restrict__ aw) {
    int b = blockIdx.x;
    int tid = threadIdx.x;  // 256
    __shared__ float red[256];
    __shared__ float s_alen;

    red[tid] = (text[b * SN + tid] != 0) ? 1.f : 0.f;
    __syncthreads();
    for (int o = 128; o > 0; o >>= 1) { if (tid < o) red[tid] += red[tid + o]; __syncthreads(); }
    if (tid == 0) d_mlen[b] = red[0];
    __syncthreads();

    red[tid] = (left[b * SN + tid] != 0) ? 1.f : 0.f;
    __syncthreads();
    for (int o = 128; o > 0; o >>= 1) { if (tid < o) red[tid] += red[tid + o]; __syncthreads(); }
    if (tid == 0) d_llen[b] = red[0];
    __syncthreads();

    red[tid] = (tid < AN && aspect[b * AN + tid] != 0) ? 1.f : 0.f;
    __syncthreads();
    for (int o = 128; o > 0; o >>= 1) { if (tid < o) red[tid] += red[tid + o]; __syncthreads(); }
    if (tid == 0) { s_alen = red[0]; d_alen[b] = red[0]; }
    __syncthreads();
    float alen = s_alen;

    float part = 0.f;
    for (int d = tid; d < EN; d += 256) {
        float s = 0.f;
        #pragma unroll
        for (int a = 0; a < AN; a++) {
            int tok = aspect[b * AN + a];
            s += embed[(size_t)tok * EN + d];
        }
        s /= alen;
        d_asp[b * EN + d] = s;
        d_et[b * EN + d] = 0.f;
        part += s * aw[901 + d];
    }
    red[tid] = part;
    __syncthreads();
    for (int o = 128; o > 0; o >>= 1) { if (tid < o) red[tid] += red[tid + o]; __syncthreads(); }
    if (tid == 0) d_casp[b] = red[0];
}

__global__ void k_zero() {
    int i = blockIdx.x * 256 + threadIdx.x;
    if (i < 2 * 2 * 300 * 256) ((float*)d_hstate)[i] = 0.f;
    if (i < 2 * 300 * 256) ((float*)d_cstate)[i] = 0.f;
}

// ---------------- input-gate GEMM with fused embedding gather ----------------
// Rows r = s*256 + b. Output layout: d_Gpre[dir][((s*1200 + n)*256 + b)]
__global__ __launch_bounds__(256) void k_gemm_in(const int* __restrict__ text,
                                                 const float* __restrict__ embed,
                                                 const float* __restrict__ fb,
                                                 const float* __restrict__ bb) {
    int dir = blockIdx.z;
    const float* wT = d_wihT[dir];
    const float* bias = dir ? bb : fb;
    float* C = d_Gpre + (size_t)dir * 65536 * 1200;

    __shared__ float As[8][128];
    __shared__ float Bs[8][128];
    __shared__ float Cs[8][128];
    int tid = threadIdx.x;
    int m0 = blockIdx.y * 128, n0 = blockIdx.x * 128;
    int s = m0 >> 8;        // tile is one s, 128 consecutive b
    int b0 = m0 & 255;
    int tx = tid & 15, ty = tid >> 4;

    float acc[8][8];
    #pragma unroll
    for (int i = 0; i < 8; i++)
        #pragma unroll
        for (int j = 0; j < 8; j++) acc[i][j] = 0.f;

    int am = tid >> 1;                   // b-row within tile
    int ak4 = (tid & 1) * 4;
    int tok = text[(b0 + am) * SN + s];  // text is [B,S]
    const float* aptr = embed + (size_t)tok * 300;
    int bn = (tid & 31) * 4;
    int bk = tid >> 5;
    bool bnval = (n0 + bn + 3) < 1200;

    for (int k0 = 0; k0 < 304; k0 += 8) {
        float4 av = make_float4(0.f, 0.f, 0.f, 0.f);
        int ka = k0 + ak4;
        if (ka <= 296) av = *(const float4*)(aptr + ka);
        As[ak4 + 0][am] = av.x;
        As[ak4 + 1][am] = av.y;
        As[ak4 + 2][am] = av.z;
        As[ak4 + 3][am] = av.w;

        float4 bv = make_float4(0.f, 0.f, 0.f, 0.f);
        int kb = k0 + bk;
        if (kb < 300 && bnval) bv = *(const float4*)(wT + (size_t)kb * 1200 + n0 + bn);
        *(float4*)&Bs[bk][bn] = bv;
        __syncthreads();

        #pragma unroll
        for (int kk = 0; kk < 8; kk++) {
            float a[8], bf[8];
            *(float4*)(a)      = *(const float4*)&As[kk][ty * 8];
            *(float4*)(a + 4)  = *(const float4*)&As[kk][ty * 8 + 4];
            *(float4*)(bf)     = *(const float4*)&Bs[kk][tx * 8];
            *(float4*)(bf + 4) = *(const float4*)&Bs[kk][tx * 8 + 4];
            #pragma unroll
            for (int i = 0; i < 8; i++)
                #pragma unroll
                for (int j = 0; j < 8; j++) acc[i][j] += a[i] * bf[j];
        }
        __syncthreads();
    }

    // staged transpose store: chunk c handles n = n0 + c*8 .. +7, coalesced over b
    int jr = tid >> 5;            // 0..7 (n-row within chunk)
    int col4 = (tid & 31) * 4;    // b offset within tile
    #pragma unroll 1
    for (int c = 0; c < 16; c++) {
        if (tx == c) {
            #pragma unroll
            for (int j = 0; j < 8; j++) {
                int n = n0 + c * 8 + j;
                float bv = (n < 1200) ? bias[n] : 0.f;
                #pragma unroll
                for (int i = 0; i < 8; i++) Cs[j][ty * 8 + i] = acc[i][j] + bv;
            }
        }
        __syncthreads();
        int n = n0 + c * 8 + jr;
        if (n < 1200)
            *(float4*)&C[((size_t)s * 1200 + n) * 256 + b0 + col4] = *(const float4*)&Cs[jr][col4];
        __syncthreads();
    }
}

// ---------------- one LSTM timestep, both directions (grid.z) ----------------
// block: 64 batch x 16 hidden units (all 4 gates). 256 threads, each 4 batch x 4 gates.
__global__ __launch_bounds__(256) void k_step(int step) {
    int dir = blockIdx.z;
    int t = dir ? (SN - 1 - step) : step;
    const float* whhT = d_whhT[dir];
    const float* hprev = d_hstate[dir][step & 1];
    float* hnext = d_hstate[dir][(step + 1) & 1];
    float* cst = d_cstate[dir];
    const float* gpre = d_Gpre + (size_t)dir * 65536 * 1200;  // [t][n][b]

    int b0 = blockIdx.x * 64;
    int u0 = blockIdx.y * 16;
    int tid = threadIdx.x;
    int ui = tid >> 4;
    int bi4 = (tid & 15) * 4;
    int u = u0 + ui;
    bool uvalid = u < 300;

    __shared__ float Wt[12][64];
    __shared__ float Ht[12][64];

    float acc[4][4];  // [batch j][gate g]
    if (uvalid) {
        #pragma unroll
        for (int g = 0; g < 4; g++) {
            float4 v = *(const float4*)&gpre[((size_t)t * 1200 + g * 300 + u) * 256 + b0 + bi4];
            acc[0][g] = v.x; acc[1][g] = v.y; acc[2][g] = v.z; acc[3][g] = v.w;
        }
    } else {
        #pragma unroll
        for (int j = 0; j < 4; j++)
            #pragma unroll
            for (int g = 0; g < 4; g++) acc[j][g] = 0.f;
    }

    int lr = tid & 63;
    int lk = tid >> 6;  // 0..3
    int rcol = u0 + (lr & 15);
    int rm = (lr >> 4) * 300 + rcol;
    bool rvalid = rcol < 300;

    for (int k0 = 0; k0 < 300; k0 += 12) {
        #pragma unroll
        for (int q = 0; q < 3; q++) {
            int kk = lk * 3 + q;
            Ht[kk][lr] = hprev[(k0 + kk) * 256 + b0 + lr];
            Wt[kk][lr] = rvalid ? whhT[(size_t)(k0 + kk) * 1200 + rm] : 0.f;
        }
        __syncthreads();
        #pragma unroll
        for (int kk = 0; kk < 12; kk++) {
            float4 hv = *(const float4*)&Ht[kk][bi4];
            float w0 = Wt[kk][ui], w1 = Wt[kk][16 + ui], w2 = Wt[kk][32 + ui], w3 = Wt[kk][48 + ui];
            acc[0][0] += hv.x * w0; acc[0][1] += hv.x * w1; acc[0][2] += hv.x * w2; acc[0][3] += hv.x * w3;
            acc[1][0] += hv.y * w0; acc[1][1] += hv.y * w1; acc[1][2] += hv.y * w2; acc[1][3] += hv.y * w3;
            acc[2][0] += hv.z * w0; acc[2][1] += hv.z * w1; acc[2][2] += hv.z * w2; acc[2][3] += hv.z * w3;
            acc[3][0] += hv.w * w0; acc[3][1] += hv.w * w1; acc[3][2] += hv.w * w2; acc[3][3] += hv.w * w3;
        }
        __syncthreads();
    }

    if (uvalid) {
        float tt = (float)t;
        #pragma unroll
        for (int j = 0; j < 4; j++) {
            int b = b0 + bi4 + j;
            float ig = sigf(acc[j][0]);
            float fg = sigf(acc[j][1]);
            float gg = tanhf(acc[j][2]);
            float og = sigf(acc[j][3]);
            float c = fg * cst[u * 256 + b] + ig * gg;
            cst[u * 256 + b] = c;
            float h = og * tanhf(c);
            hnext[u * 256 + b] = h;
            float llv = d_llen[b], alv = d_alen[b], Mv = d_mlen[b];
            float w;
            if (tt < llv) w = 1.f - (llv - tt) / Mv;
            else if (tt < llv + alv) w = 1.f;
            else if (tt < Mv) w = 1.f - (tt - llv - alv + 1.f) / Mv;
            else w = 0.f;
            d_mem[((size_t)b * SN + t) * DN + dir * 300 + u] = h * w;
        }
    }
}

// ---------------- fill u column + gm = mem . attn_w[0:601]  ----------------
__global__ void k_gm(const float* __restrict__ aw) {
    int warp = threadIdx.x >> 5, lane = threadIdx.x & 31;
    int r = blockIdx.x * 8 + warp;
    int b = r >> 8, s = r & 255;
    float llv = d_llen[b], alv = d_alen[b], Mv = d_mlen[b];
    float ss = (float)s;
    float uu;
    if (ss < llv) uu = ss - llv;
    else if (ss < llv + alv) uu = 0.f;
    else if (ss < Mv) uu = ss - llv - alv + 1.f;
    else uu = 1.f;

    float* mrow = d_mem + (size_t)r * DN;
    float part = 0.f;
    for (int d = lane; d < DN; d += 32) {
        float v;
        if (d == 600) { v = uu; mrow[600] = uu; }
        else v = mrow[d];
        part += v * aw[d];
    }
    #pragma unroll
    for (int o = 16; o > 0; o >>= 1) part += __shfl_down_sync(0xffffffffu, part, o);
    if (lane == 0) d_gmT[s * BN + b] = part;
}

// ---------------- attention layer pieces ----------------
__global__ void k_gofs(const float* __restrict__ aw, const float* __restrict__ ab) {
    int b = blockIdx.x, tid = threadIdx.x;  // 128
    __shared__ float red[128];
    float p = 0.f;
    for (int k = tid; k < EN; k += 128) p += d_et[b * EN + k] * aw[601 + k];
    red[tid] = p;
    __syncthreads();
    for (int o = 64; o > 0; o >>= 1) { if (tid < o) red[tid] += red[tid + o]; __syncthreads(); }
    if (tid == 0) d_gofs[b] = red[0] + d_casp[b] + ab[0];
}

__global__ void k_softmax() {
    int s = blockIdx.x, b = threadIdx.x;
    __shared__ float red[256];
    float g = d_gmT[s * BN + b] + d_gofs[b];
    red[b] = g;
    __syncthreads();
    for (int o = 128; o > 0; o >>= 1) { if (b < o) red[b] = fmaxf(red[b], red[b + o]); __syncthreads(); }
    float mx = red[0];
    __syncthreads();
    float e = expf(g - mx);
    red[b] = e;
    __syncthreads();
    for (int o = 128; o > 0; o >>= 1) { if (b < o) red[b] += red[b + o]; __syncthreads(); }
    d_alphaT[s * BN + b] = e / red[0];
}

__global__ void k_isum() {
    int b = blockIdx.x, tid = threadIdx.x;  // 256
    __shared__ float al[256];
    al[tid] = d_alphaT[tid * BN + b];
    __syncthreads();
    float a0 = 0.f, a1 = 0.f, a2 = 0.f;
    int d0 = tid, d1 = tid + 256, d2 = tid + 512;
    bool v2 = d2 < DN;
    int d2c = v2 ? d2 : 600;
    const float* mb = d_mem + (size_t)b * SN * DN;
    #pragma unroll 4
    for (int s = 0; s < SN; s++) {
        float a = al[s];
        const float* mr = mb + (size_t)s * DN;
        a0 += a * mr[d0];
        a1 += a * mr[d1];
        a2 += a * mr[d2c];
    }
    d_ivec[b * DN + d0] = a0;
    d_ivec[b * DN + d1] = a1;
    if (v2) d_ivec[b * DN + d2] = a2;
}

__global__ void k_gru(const float* __restrict__ bih, const float* __restrict__ bhh) {
    int b = blockIdx.x, tid = threadIdx.x;  // 256
    __shared__ float si[601];
    __shared__ float se[300];
    __shared__ float gbuf[1800];
    for (int k = tid; k < DN; k += 256) si[k] = d_ivec[b * DN + k];
    for (int k = tid; k < EN; k += 256) se[k] = d_et[b * EN + k];
    __syncthreads();

    int r0 = tid, r1 = tid + 256, r2 = tid + 512, r3 = tid + 768;
    bool v3 = r3 < 900;
    int r3c = v3 ? r3 : 899;
    float a0 = bih[r0], a1 = bih[r1], a2 = bih[r2], a3 = bih[r3c];
    for (int k = 0; k < DN; k++) {
        float v = si[k];
        const float* w = d_gwihT + (size_t)k * 900;
        a0 += v * w[r0]; a1 += v * w[r1]; a2 += v * w[r2]; a3 += v * w[r3c];
    }
    gbuf[r0] = a0; gbuf[r1] = a1; gbuf[r2] = a2;
    if (v3) gbuf[r3] = a3;

    float h0 = bhh[r0], h1 = bhh[r1], h2 = bhh[r2], h3 = bhh[r3c];
    for (int k = 0; k < EN; k++) {
        float v = se[k];
        const float* w = d_gwhhT + (size_t)k * 900;
        h0 += v * w[r0]; h1 += v * w[r1]; h2 += v * w[r2]; h3 += v * w[r3c];
    }
    gbuf[900 + r0] = h0; gbuf[900 + r1] = h1; gbuf[900 + r2] = h2;
    if (v3) gbuf[900 + r3] = h3;
    __syncthreads();

    for (int e = tid; e < EN; e += 256) {
        float rr = sigf(gbuf[e] + gbuf[900 + e]);
        float zz = sigf(gbuf[300 + e] + gbuf[1200 + e]);
        float nn = tanhf(gbuf[600 + e] + rr * gbuf[1500 + e]);
        d_et[b * EN + e] = (1.f - zz) * nn + zz * se[e];
    }
}

__global__ void k_dense(const float* __restrict__ dw, const float* __restrict__ db,
                        float* __restrict__ out) {
    int b = blockIdx.x;
    int p = threadIdx.x >> 5;
    int lane = threadIdx.x & 31;
    if (p < POLN) {
        float s = 0.f;
        for (int k = lane; k < EN; k += 32) s += d_et[b * EN + k] * dw[p * EN + k];
        #pragma unroll
        for (int o = 16; o > 0; o >>= 1) s += __shfl_down_sync(0xffffffffu, s, o);
        if (lane == 0) out[b * POLN + p] = s + db[p];
    }
}

// ---------------- launcher ----------------
extern "C" void kernel_launch(void* const* d_in, const int* in_sizes, int n_in,
                              void* d_out, int out_size) {
    const int* text = (const int*)d_in[0];
    const int* aspect = (const int*)d_in[1];
    const int* left = (const int*)d_in[2];
    const float* embed = (const float*)d_in[3];
    const float* fwih = (const float*)d_in[4];
    const float* fwhh = (const float*)d_in[5];
    const float* fb = (const float*)d_in[6];
    const float* bwih = (const float*)d_in[7];
    const float* bwhh = (const float*)d_in[8];
    const float* bb = (const float*)d_in[9];
    const float* aw = (const float*)d_in[10];
    const float* ab = (const float*)d_in[11];
    const float* gwih = (const float*)d_in[12];
    const float* gwhh = (const float*)d_in[13];
    const float* gbih = (const float*)d_in[14];
    const float* gbhh = (const float*)d_in[15];
    const float* dw = (const float*)d_in[16];
    const float* db = (const float*)d_in[17];
    float* out = (float*)d_out;

    k_transpose_all<<<dim3(19, 38, 6), dim3(32, 8)>>>(fwih, fwhh, bwih, bwhh, gwih, gwhh);
    k_prep_b<<<256, 256>>>(text, left, aspect, embed, aw);
    k_zero<<<1200, 256>>>();
    k_gemm_in<<<dim3(10, 512, 2), 256>>>(text, embed, fb, bb);
    for (int st = 0; st < SN; st++)
        k_step<<<dim3(4, 19, 2), 256>>>(st);
    k_gm<<<8192, 256>>>(aw);
    for (int l = 0; l < 4; l++) {
        k_gofs<<<256, 128>>>(aw, ab);
        k_softmax<<<256, 256>>>();
        k_isum<<<256, 256>>>();
        k_gru<<<256, 256>>>(gbih, gbhh);
    }
    k_dense<<<256, 96>>>(dw, db, out);
}

// round 4
// speedup vs baseline: 1.0332x; 1.0332x over previous
#include <cuda_runtime.h>
#include <math.h>

#define BN 256
#define SN 256
#define EN 300
#define HN 300
#define G4 1200
#define DN 601
#define AN 16
#define POLN 3
#define KC 30

// ---------------- static device scratch (no allocations allowed) ----------------
__device__ float d_wihT[2][300 * 1200];      // input weights, k-major
__device__ float d_whhT[2][300 * 1200];      // recurrent weights, k-major
__device__ float d_gwihT[601 * 900];         // GRU W_ih^T  (k-major)
__device__ float d_gwhhT[300 * 900];         // GRU W_hh^T  (k-major)
__device__ float d_Gpre[2 * 65536 * 1200];   // input gates, layout [dir][t][n][b]
__device__ float d_mem[65536 * 601];         // location-weighted memory [b][s][d]
__device__ float d_hstate[2][2][300 * 256];  // [dir][parity][u][b]
__device__ float d_cstate[2][300 * 256];     // [dir][u][b]
__device__ float d_gmT[65536];               // [s][b]  mem-part of attention logit
__device__ float d_alphaT[65536];            // [s][b]
__device__ float d_gofs[256];
__device__ float d_asp[256 * 300];
__device__ float d_casp[256];
__device__ float d_et[256 * 300];
__device__ float d_ivec[256 * 601];
__device__ float d_llen[256], d_alen[256], d_mlen[256];

__device__ __forceinline__ float sigf(float x) { return 1.f / (1.f + expf(-x)); }

// ---------------- weight transposes ----------------
__global__ void k_transpose_all(const float* __restrict__ fwih, const float* __restrict__ fwhh,
                                const float* __restrict__ bwih, const float* __restrict__ bwhh,
                                const float* __restrict__ gwih, const float* __restrict__ gwhh) {
    int id = blockIdx.z;
    const float* src;
    float* dst;
    int R, C;
    switch (id) {
        case 0: src = fwih; dst = d_wihT[0]; R = 1200; C = 300; break;
        case 1: src = fwhh; dst = d_whhT[0]; R = 1200; C = 300; break;
        case 2: src = bwih; dst = d_wihT[1]; R = 1200; C = 300; break;
        case 3: src = bwhh; dst = d_whhT[1]; R = 1200; C = 300; break;
        case 4: src = gwih; dst = d_gwihT;   R = 900;  C = 601; break;
        default: src = gwhh; dst = d_gwhhT;  R = 900;  C = 300; break;
    }
    __shared__ float tile[32][33];
    int c0 = blockIdx.x * 32, r0 = blockIdx.y * 32;
    int x = threadIdx.x, y = threadIdx.y;  // 32 x 8
    #pragma unroll
    for (int i = 0; i < 32; i += 8) {
        int r = r0 + y + i, c = c0 + x;
        if (r < R && c < C) tile[y + i][x] = src[(size_t)r * C + c];
    }
    __syncthreads();
    #pragma unroll
    for (int i = 0; i < 32; i += 8) {
        int c = c0 + y + i, r = r0 + x;
        if (c < C && r < R) dst[(size_t)c * R + r] = tile[x][y + i];
    }
}

// ---------------- lengths / aspect vector / init ----------------
__global__ void k_prep_b(const int* __restrict__ text, const int* __restrict__ left,
                         const int* __restrict__ aspect, const float* __restrict__ embed,
                         const float* __restrict__ aw) {
    int b = blockIdx.x;
    int tid = threadIdx.x;  // 256
    __shared__ float red[256];
    __shared__ float s_alen;

    red[tid] = (text[b * SN + tid] != 0) ? 1.f : 0.f;
    __syncthreads();
    for (int o = 128; o > 0; o >>= 1) { if (tid < o) red[tid] += red[tid + o]; __syncthreads(); }
    if (tid == 0) d_mlen[b] = red[0];
    __syncthreads();

    red[tid] = (left[b * SN + tid] != 0) ? 1.f : 0.f;
    __syncthreads();
    for (int o = 128; o > 0; o >>= 1) { if (tid < o) red[tid] += red[tid + o]; __syncthreads(); }
    if (tid == 0) d_llen[b] = red[0];
    __syncthreads();

    red[tid] = (tid < AN && aspect[b * AN + tid] != 0) ? 1.f : 0.f;
    __syncthreads();
    for (int o = 128; o > 0; o >>= 1) { if (tid < o) red[tid] += red[tid + o]; __syncthreads(); }
    if (tid == 0) { s_alen = red[0]; d_alen[b] = red[0]; }
    __syncthreads();
    float alen = s_alen;

    float part = 0.f;
    for (int d = tid; d < EN; d += 256) {
        float s = 0.f;
        #pragma unroll
        for (int a = 0; a < AN; a++) {
            int tok = aspect[b * AN + a];
            s += embed[(size_t)tok * EN + d];
        }
        s /= alen;
        d_asp[b * EN + d] = s;
        d_et[b * EN + d] = 0.f;
        part += s * aw[901 + d];
    }
    red[tid] = part;
    __syncthreads();
    for (int o = 128; o > 0; o >>= 1) { if (tid < o) red[tid] += red[tid + o]; __syncthreads(); }
    if (tid == 0) d_casp[b] = red[0];
}

__global__ void k_zero() {
    int i = blockIdx.x * 256 + threadIdx.x;
    if (i < 2 * 2 * 300 * 256) ((float*)d_hstate)[i] = 0.f;
    if (i < 2 * 300 * 256) ((float*)d_cstate)[i] = 0.f;
}

// ---------------- input-gate GEMM with fused embedding gather ----------------
// Rows r = s*256 + b. Output layout: d_Gpre[dir][((s*1200 + n)*256 + b)]
__global__ __launch_bounds__(256) void k_gemm_in(const int* __restrict__ text,
                                                 const float* __restrict__ embed,
                                                 const float* __restrict__ fb,
                                                 const float* __restrict__ bb) {
    int dir = blockIdx.z;
    const float* wT = d_wihT[dir];
    const float* bias = dir ? bb : fb;
    float* C = d_Gpre + (size_t)dir * 65536 * 1200;

    __shared__ float As[8][128];
    __shared__ float Bs[8][128];
    __shared__ float Cs[8][128];
    int tid = threadIdx.x;
    int m0 = blockIdx.y * 128, n0 = blockIdx.x * 128;
    int s = m0 >> 8;        // tile is one s, 128 consecutive b
    int b0 = m0 & 255;
    int tx = tid & 15, ty = tid >> 4;

    float acc[8][8];
    #pragma unroll
    for (int i = 0; i < 8; i++)
        #pragma unroll
        for (int j = 0; j < 8; j++) acc[i][j] = 0.f;

    int am = tid >> 1;                   // b-row within tile
    int ak4 = (tid & 1) * 4;
    int tok = text[(b0 + am) * SN + s];  // text is [B,S]
    const float* aptr = embed + (size_t)tok * 300;
    int bn = (tid & 31) * 4;
    int bk = tid >> 5;
    bool bnval = (n0 + bn + 3) < 1200;

    for (int k0 = 0; k0 < 304; k0 += 8) {
        float4 av = make_float4(0.f, 0.f, 0.f, 0.f);
        int ka = k0 + ak4;
        if (ka <= 296) av = *(const float4*)(aptr + ka);
        As[ak4 + 0][am] = av.x;
        As[ak4 + 1][am] = av.y;
        As[ak4 + 2][am] = av.z;
        As[ak4 + 3][am] = av.w;

        float4 bv = make_float4(0.f, 0.f, 0.f, 0.f);
        int kb = k0 + bk;
        if (kb < 300 && bnval) bv = *(const float4*)(wT + (size_t)kb * 1200 + n0 + bn);
        *(float4*)&Bs[bk][bn] = bv;
        __syncthreads();

        #pragma unroll
        for (int kk = 0; kk < 8; kk++) {
            float a[8], bf[8];
            *(float4*)(a)      = *(const float4*)&As[kk][ty * 8];
            *(float4*)(a + 4)  = *(const float4*)&As[kk][ty * 8 + 4];
            *(float4*)(bf)     = *(const float4*)&Bs[kk][tx * 8];
            *(float4*)(bf + 4) = *(const float4*)&Bs[kk][tx * 8 + 4];
            #pragma unroll
            for (int i = 0; i < 8; i++)
                #pragma unroll
                for (int j = 0; j < 8; j++) acc[i][j] += a[i] * bf[j];
        }
        __syncthreads();
    }

    // staged transpose store: chunk c handles n = n0 + c*8 .. +7, coalesced over b
    int jr = tid >> 5;            // 0..7 (n-row within chunk)
    int col4 = (tid & 31) * 4;    // b offset within tile
    #pragma unroll 1
    for (int c = 0; c < 16; c++) {
        if (tx == c) {
            #pragma unroll
            for (int j = 0; j < 8; j++) {
                int n = n0 + c * 8 + j;
                float bv = (n < 1200) ? bias[n] : 0.f;
                #pragma unroll
                for (int i = 0; i < 8; i++) Cs[j][ty * 8 + i] = acc[i][j] + bv;
            }
        }
        __syncthreads();
        int n = n0 + c * 8 + jr;
        if (n < 1200)
            *(float4*)&C[((size_t)s * 1200 + n) * 256 + b0 + col4] = *(const float4*)&Cs[jr][col4];
        __syncthreads();
    }
}

// ---------------- one LSTM timestep, both directions (grid.z) ----------------
// Block = (dir, 128 b, 8 u x 4 gates). 256 threads: warp = u-offset (W broadcast),
// lane = 4-batch group. W tile (38.4KB) staged once; h double-buffered in KC chunks.
__global__ __launch_bounds__(256) void k_step(int step) {
    int dir = blockIdx.z;
    int t = dir ? (SN - 1 - step) : step;
    const float* whhT = d_whhT[dir];
    const float* hprev = d_hstate[dir][step & 1];
    float* hnext = d_hstate[dir][(step + 1) & 1];
    float* cst = d_cstate[dir];
    const float* gpre = d_Gpre + (size_t)dir * 65536 * 1200;  // [t][n][b]

    int u0 = blockIdx.x * 8;
    int b0 = blockIdx.y * 128;
    int tid = threadIdx.x;
    int cg = tid >> 5;   // warp = u-offset 0..7
    int bg = tid & 31;   // 4-batch group
    int u = u0 + cg;
    int uc = (u < 300) ? u : 0;
    int b = b0 + bg * 4;

    extern __shared__ float smem[];
    float* Ws = smem;          // [300][32]  col = uoff*4 + gate
    float* Hs = smem + 9600;   // [2][KC][128]

    // stage full W tile (one-time)
    {
        int lane = tid & 31, ww = tid >> 5;
        int g = lane >> 3;
        int uu = u0 + (lane & 7);
        int col = (lane & 7) * 4 + g;
        const float* wp = whhT + g * 300 + ((uu < 300) ? uu : 0);
        float zf = (uu < 300) ? 1.f : 0.f;
        for (int k = ww; k < 300; k += 8)
            Ws[k * 32 + col] = zf * wp[(size_t)k * 1200];
    }

    // acc init from precomputed input gates
    float acc[4][4];  // [batch j][gate g]
    {
        const float* gp = gpre + (size_t)t * 1200 * 256;
        #pragma unroll
        for (int g = 0; g < 4; g++) {
            float4 v = *(const float4*)&gp[(size_t)(g * 300 + uc) * 256 + b];
            acc[0][g] = v.x; acc[1][g] = v.y; acc[2][g] = v.z; acc[3][g] = v.w;
        }
    }

    // h chunk 0 -> shared
    #pragma unroll
    for (int i = 0; i < 4; i++) {
        int idx = tid + i * 256;
        if (idx < 8 * KC * 4)  // 960 float4s
            *(float4*)&Hs[(idx >> 5) * 128 + (idx & 31) * 4] =
                *(const float4*)&hprev[(idx >> 5) * 256 + b0 + (idx & 31) * 4];
    }
    __syncthreads();

    #pragma unroll 1
    for (int c = 0; c < 10; c++) {
        const float* hsc = Hs + (c & 1) * KC * 128;
        float4 pf[4];
        if (c < 9) {
            int kb = (c + 1) * KC;
            #pragma unroll
            for (int i = 0; i < 4; i++) {
                int idx = tid + i * 256;
                if (idx < 960)
                    pf[i] = *(const float4*)&hprev[(size_t)(kb + (idx >> 5)) * 256 + b0 + (idx & 31) * 4];
            }
        }
        const float* wbase = Ws + c * KC * 32 + cg * 4;
        #pragma unroll
        for (int kk = 0; kk < KC; kk++) {
            float4 hv = *(const float4*)&hsc[kk * 128 + bg * 4];
            float4 wv = *(const float4*)&wbase[kk * 32];
            acc[0][0] += hv.x * wv.x; acc[0][1] += hv.x * wv.y; acc[0][2] += hv.x * wv.z; acc[0][3] += hv.x * wv.w;
            acc[1][0] += hv.y * wv.x; acc[1][1] += hv.y * wv.y; acc[1][2] += hv.y * wv.z; acc[1][3] += hv.y * wv.w;
            acc[2][0] += hv.z * wv.x; acc[2][1] += hv.z * wv.y; acc[2][2] += hv.z * wv.z; acc[2][3] += hv.z * wv.w;
            acc[3][0] += hv.w * wv.x; acc[3][1] += hv.w * wv.y; acc[3][2] += hv.w * wv.z; acc[3][3] += hv.w * wv.w;
        }
        if (c < 9) {
            float* hsn = Hs + ((c + 1) & 1) * KC * 128;
            #pragma unroll
            for (int i = 0; i < 4; i++) {
                int idx = tid + i * 256;
                if (idx < 960)
                    *(float4*)&hsn[(idx >> 5) * 128 + (idx & 31) * 4] = pf[i];
            }
            __syncthreads();
        }
    }

    if (u < 300) {
        float4 cv = *(const float4*)&cst[u * 256 + b];
        float cc[4] = {cv.x, cv.y, cv.z, cv.w};
        float hh[4];
        float tt = (float)t;
        #pragma unroll
        for (int j = 0; j < 4; j++) {
            float ig = sigf(acc[j][0]);
            float fg = sigf(acc[j][1]);
            float gg = tanhf(acc[j][2]);
            float og = sigf(acc[j][3]);
            float c2 = fg * cc[j] + ig * gg;
            cc[j] = c2;
            hh[j] = og * tanhf(c2);
            int bj = b + j;
            float llv = d_llen[bj], alv = d_alen[bj], Mv = d_mlen[bj];
            float w;
            if (tt < llv) w = 1.f - (llv - tt) / Mv;
            else if (tt < llv + alv) w = 1.f;
            else if (tt < Mv) w = 1.f - (tt - llv - alv + 1.f) / Mv;
            else w = 0.f;
            d_mem[((size_t)bj * SN + t) * DN + dir * 300 + u] = hh[j] * w;
        }
        *(float4*)&cst[u * 256 + b] = make_float4(cc[0], cc[1], cc[2], cc[3]);
        *(float4*)&hnext[u * 256 + b] = make_float4(hh[0], hh[1], hh[2], hh[3]);
    }
}

// ---------------- fill u column + gm = mem . attn_w[0:601]  ----------------
__global__ void k_gm(const float* __restrict__ aw) {
    int warp = threadIdx.x >> 5, lane = threadIdx.x & 31;
    int r = blockIdx.x * 8 + warp;
    int b = r >> 8, s = r & 255;
    float llv = d_llen[b], alv = d_alen[b], Mv = d_mlen[b];
    float ss = (float)s;
    float uu;
    if (ss < llv) uu = ss - llv;
    else if (ss < llv + alv) uu = 0.f;
    else if (ss < Mv) uu = ss - llv - alv + 1.f;
    else uu = 1.f;

    float* mrow = d_mem + (size_t)r * DN;
    float part = 0.f;
    for (int d = lane; d < DN; d += 32) {
        float v;
        if (d == 600) { v = uu; mrow[600] = uu; }
        else v = mrow[d];
        part += v * aw[d];
    }
    #pragma unroll
    for (int o = 16; o > 0; o >>= 1) part += __shfl_down_sync(0xffffffffu, part, o);
    if (lane == 0) d_gmT[s * BN + b] = part;
}

// ---------------- attention layer pieces ----------------
__global__ void k_gofs(const float* __restrict__ aw, const float* __restrict__ ab) {
    int b = blockIdx.x, tid = threadIdx.x;  // 128
    __shared__ float red[128];
    float p = 0.f;
    for (int k = tid; k < EN; k += 128) p += d_et[b * EN + k] * aw[601 + k];
    red[tid] = p;
    __syncthreads();
    for (int o = 64; o > 0; o >>= 1) { if (tid < o) red[tid] += red[tid + o]; __syncthreads(); }
    if (tid == 0) d_gofs[b] = red[0] + d_casp[b] + ab[0];
}

__global__ void k_softmax() {
    int s = blockIdx.x, b = threadIdx.x;
    __shared__ float red[256];
    float g = d_gmT[s * BN + b] + d_gofs[b];
    red[b] = g;
    __syncthreads();
    for (int o = 128; o > 0; o >>= 1) { if (b < o) red[b] = fmaxf(red[b], red[b + o]); __syncthreads(); }
    float mx = red[0];
    __syncthreads();
    float e = expf(g - mx);
    red[b] = e;
    __syncthreads();
    for (int o = 128; o > 0; o >>= 1) { if (b < o) red[b] += red[b + o]; __syncthreads(); }
    d_alphaT[s * BN + b] = e / red[0];
}

__global__ void k_isum() {
    int b = blockIdx.x, tid = threadIdx.x;  // 256
    __shared__ float al[256];
    al[tid] = d_alphaT[tid * BN + b];
    __syncthreads();
    float a0 = 0.f, a1 = 0.f, a2 = 0.f;
    int d0 = tid, d1 = tid + 256, d2 = tid + 512;
    bool v2 = d2 < DN;
    int d2c = v2 ? d2 : 600;
    const float* mb = d_mem + (size_t)b * SN * DN;
    #pragma unroll 4
    for (int s = 0; s < SN; s++) {
        float a = al[s];
        const float* mr = mb + (size_t)s * DN;
        a0 += a * mr[d0];
        a1 += a * mr[d1];
        a2 += a * mr[d2c];
    }
    d_ivec[b * DN + d0] = a0;
    d_ivec[b * DN + d1] = a1;
    if (v2) d_ivec[b * DN + d2] = a2;
}

// 4 batch elements per block: W rows loaded once, reused x4
__global__ __launch_bounds__(256) void k_gru(const float* __restrict__ bih,
                                             const float* __restrict__ bhh) {
    int b0 = blockIdx.x * 4;
    int tid = threadIdx.x;  // 256
    __shared__ float si[4][608];
    __shared__ float se[4][304];
    __shared__ float gi[4][904];
    __shared__ float gh[4][904];
    #pragma unroll
    for (int bb = 0; bb < 4; bb++) {
        for (int k = tid; k < DN; k += 256) si[bb][k] = d_ivec[(b0 + bb) * DN + k];
        for (int k = tid; k < EN; k += 256) se[bb][k] = d_et[(b0 + bb) * EN + k];
    }
    __syncthreads();

    int r0 = tid, r1 = tid + 256, r2 = tid + 512, r3 = tid + 768;
    bool v3 = r3 < 900;
    int r3c = v3 ? r3 : 899;

    float acc[4][4];
    #pragma unroll
    for (int bb = 0; bb < 4; bb++) {
        acc[bb][0] = bih[r0]; acc[bb][1] = bih[r1]; acc[bb][2] = bih[r2]; acc[bb][3] = bih[r3c];
    }
    for (int k = 0; k < DN; k++) {
        const float* w = d_gwihT + (size_t)k * 900;
        float w0 = w[r0], w1 = w[r1], w2 = w[r2], w3 = w[r3c];
        #pragma unroll
        for (int bb = 0; bb < 4; bb++) {
            float v = si[bb][k];
            acc[bb][0] += v * w0; acc[bb][1] += v * w1; acc[bb][2] += v * w2; acc[bb][3] += v * w3;
        }
    }
    #pragma unroll
    for (int bb = 0; bb < 4; bb++) {
        gi[bb][r0] = acc[bb][0]; gi[bb][r1] = acc[bb][1]; gi[bb][r2] = acc[bb][2];
        if (v3) gi[bb][r3] = acc[bb][3];
    }

    #pragma unroll
    for (int bb = 0; bb < 4; bb++) {
        acc[bb][0] = bhh[r0]; acc[bb][1] = bhh[r1]; acc[bb][2] = bhh[r2]; acc[bb][3] = bhh[r3c];
    }
    for (int k = 0; k < EN; k++) {
        const float* w = d_gwhhT + (size_t)k * 900;
        float w0 = w[r0], w1 = w[r1], w2 = w[r2], w3 = w[r3c];
        #pragma unroll
        for (int bb = 0; bb < 4; bb++) {
            float v = se[bb][k];
            acc[bb][0] += v * w0; acc[bb][1] += v * w1; acc[bb][2] += v * w2; acc[bb][3] += v * w3;
        }
    }
    #pragma unroll
    for (int bb = 0; bb < 4; bb++) {
        gh[bb][r0] = acc[bb][0]; gh[bb][r1] = acc[bb][1]; gh[bb][r2] = acc[bb][2];
        if (v3) gh[bb][r3] = acc[bb][3];
    }
    __syncthreads();

    for (int e = tid; e < EN; e += 256) {
        #pragma unroll
        for (int bb = 0; bb < 4; bb++) {
            float rr = sigf(gi[bb][e] + gh[bb][e]);
            float zz = sigf(gi[bb][300 + e] + gh[bb][300 + e]);
            float nn = tanhf(gi[bb][600 + e] + rr * gh[bb][600 + e]);
            d_et[(b0 + bb) * EN + e] = (1.f - zz) * nn + zz * se[bb][e];
        }
    }
}

__global__ void k_dense(const float* __restrict__ dw, const float* __restrict__ db,
                        float* __restrict__ out) {
    int b = blockIdx.x;
    int p = threadIdx.x >> 5;
    int lane = threadIdx.x & 31;
    if (p < POLN) {
        float s = 0.f;
        for (int k = lane; k < EN; k += 32) s += d_et[b * EN + k] * dw[p * EN + k];
        #pragma unroll
        for (int o = 16; o > 0; o >>= 1) s += __shfl_down_sync(0xffffffffu, s, o);
        if (lane == 0) out[b * POLN + p] = s + db[p];
    }
}

// ---------------- launcher ----------------
extern "C" void kernel_launch(void* const* d_in, const int* in_sizes, int n_in,
                              void* d_out, int out_size) {
    const int* text = (const int*)d_in[0];
    const int* aspect = (const int*)d_in[1];
    const int* left = (const int*)d_in[2];
    const float* embed = (const float*)d_in[3];
    const float* fwih = (const float*)d_in[4];
    const float* fwhh = (const float*)d_in[5];
    const float* fb = (const float*)d_in[6];
    const float* bwih = (const float*)d_in[7];
    const float* bwhh = (const float*)d_in[8];
    const float* bb = (const float*)d_in[9];
    const float* aw = (const float*)d_in[10];
    const float* ab = (const float*)d_in[11];
    const float* gwih = (const float*)d_in[12];
    const float* gwhh = (const float*)d_in[13];
    const float* gbih = (const float*)d_in[14];
    const float* gbhh = (const float*)d_in[15];
    const float* dw = (const float*)d_in[16];
    const float* db = (const float*)d_in[17];
    float* out = (float*)d_out;

    const int step_smem = (9600 + 2 * KC * 128) * 4;  // 69120 B
    cudaFuncSetAttribute(k_step, cudaFuncAttributeMaxDynamicSharedMemorySize, step_smem);

    k_transpose_all<<<dim3(19, 38, 6), dim3(32, 8)>>>(fwih, fwhh, bwih, bwhh, gwih, gwhh);
    k_prep_b<<<256, 256>>>(text, left, aspect, embed, aw);
    k_zero<<<1200, 256>>>();
    k_gemm_in<<<dim3(10, 512, 2), 256>>>(text, embed, fb, bb);
    for (int st = 0; st < SN; st++)
        k_step<<<dim3(38, 2, 2), 256, step_smem>>>(st);
    k_gm<<<8192, 256>>>(aw);
    for (int l = 0; l < 4; l++) {
        k_gofs<<<256, 128>>>(aw, ab);
        k_softmax<<<256, 256>>>();
        k_isum<<<256, 256>>>();
        k_gru<<<64, 256>>>(gbih, gbhh);
    }
    k_dense<<<256, 96>>>(dw, db, out);
}

// round 5
// speedup vs baseline: 1.2651x; 1.2245x over previous
#include <cuda_runtime.h>
#include <math.h>

#define BN 256
#define SN 256
#define EN 300
#define HN 300
#define G4 1200
#define DN 601
#define AN 16
#define POLN 3
#define KC 30
#define UB 10     // u-units per step block
#define NUB 30    // number of u-blocks (30*10 = 300)

// ---------------- static device scratch (no allocations allowed) ----------------
__device__ float d_wihT[2][300 * 1200];      // input weights, k-major
__device__ float d_whhT[2][300 * 1200];      // recurrent weights, k-major
__device__ float d_wstep[2][NUB][300 * 40];  // step weights: [dir][ub][k][uoff*4+g]
__device__ float d_gwihT[601 * 900];         // GRU W_ih^T  (k-major)
__device__ float d_gwhhT[300 * 900];         // GRU W_hh^T  (k-major)
__device__ float d_Gpre[2 * 65536 * 1200];   // input gates, layout [dir][t][n][b]
__device__ float d_mem[65536 * 601];         // location-weighted memory [b][s][d]
__device__ float d_hstate[2][2][300 * 256];  // [dir][parity][u][b]
__device__ float d_cstate[2][300 * 256];     // [dir][u][b]
__device__ float d_gmT[65536];               // [s][b]
__device__ float d_alphaT[65536];            // [s][b]
__device__ float d_gofs[256];
__device__ float d_asp[256 * 300];
__device__ float d_casp[256];
__device__ float d_et[256 * 300];
__device__ float d_ivec[256 * 601];
__device__ float d_llen[256], d_alen[256], d_mlen[256];

__device__ __forceinline__ float sigf(float x) { return 1.f / (1.f + expf(-x)); }

// ---------------- weight transposes ----------------
__global__ void k_transpose_all(const float* __restrict__ fwih, const float* __restrict__ fwhh,
                                const float* __restrict__ bwih, const float* __restrict__ bwhh,
                                const float* __restrict__ gwih, const float* __restrict__ gwhh) {
    int id = blockIdx.z;
    const float* src;
    float* dst;
    int R, C;
    switch (id) {
        case 0: src = fwih; dst = d_wihT[0]; R = 1200; C = 300; break;
        case 1: src = fwhh; dst = d_whhT[0]; R = 1200; C = 300; break;
        case 2: src = bwih; dst = d_wihT[1]; R = 1200; C = 300; break;
        case 3: src = bwhh; dst = d_whhT[1]; R = 1200; C = 300; break;
        case 4: src = gwih; dst = d_gwihT;   R = 900;  C = 601; break;
        default: src = gwhh; dst = d_gwhhT;  R = 900;  C = 300; break;
    }
    __shared__ float tile[32][33];
    int c0 = blockIdx.x * 32, r0 = blockIdx.y * 32;
    int x = threadIdx.x, y = threadIdx.y;  // 32 x 8
    #pragma unroll
    for (int i = 0; i < 32; i += 8) {
        int r = r0 + y + i, c = c0 + x;
        if (r < R && c < C) tile[y + i][x] = src[(size_t)r * C + c];
    }
    __syncthreads();
    #pragma unroll
    for (int i = 0; i < 32; i += 8) {
        int c = c0 + y + i, r = r0 + x;
        if (c < C && r < R) dst[(size_t)c * R + r] = tile[x][y + i];
    }
}

// build d_wstep from d_whhT (one block per (dir, ub))
__global__ void k_wstep() {
    int dir = blockIdx.y;
    int ub = blockIdx.x;
    const float* w = d_whhT[dir];
    float* dst = d_wstep[dir][ub];
    for (int i = threadIdx.x; i < 300 * 40; i += blockDim.x) {
        int k = i / 40;
        int col = i % 40;
        int uoff = col >> 2, g = col & 3;
        dst[i] = w[(size_t)k * 1200 + g * 300 + ub * UB + uoff];
    }
}

// ---------------- lengths / aspect vector / init ----------------
__global__ void k_prep_b(const int* __restrict__ text, const int* __restrict__ left,
                         const int* __restrict__ aspect, const float* __restrict__ embed,
                         const float* __restrict__ aw) {
    int b = blockIdx.x;
    int tid = threadIdx.x;  // 256
    __shared__ float red[256];
    __shared__ float s_alen;

    red[tid] = (text[b * SN + tid] != 0) ? 1.f : 0.f;
    __syncthreads();
    for (int o = 128; o > 0; o >>= 1) { if (tid < o) red[tid] += red[tid + o]; __syncthreads(); }
    if (tid == 0) d_mlen[b] = red[0];
    __syncthreads();

    red[tid] = (left[b * SN + tid] != 0) ? 1.f : 0.f;
    __syncthreads();
    for (int o = 128; o > 0; o >>= 1) { if (tid < o) red[tid] += red[tid + o]; __syncthreads(); }
    if (tid == 0) d_llen[b] = red[0];
    __syncthreads();

    red[tid] = (tid < AN && aspect[b * AN + tid] != 0) ? 1.f : 0.f;
    __syncthreads();
    for (int o = 128; o > 0; o >>= 1) { if (tid < o) red[tid] += red[tid + o]; __syncthreads(); }
    if (tid == 0) { s_alen = red[0]; d_alen[b] = red[0]; }
    __syncthreads();
    float alen = s_alen;

    float part = 0.f;
    for (int d = tid; d < EN; d += 256) {
        float s = 0.f;
        #pragma unroll
        for (int a = 0; a < AN; a++) {
            int tok = aspect[b * AN + a];
            s += embed[(size_t)tok * EN + d];
        }
        s /= alen;
        d_asp[b * EN + d] = s;
        d_et[b * EN + d] = 0.f;
        part += s * aw[901 + d];
    }
    red[tid] = part;
    __syncthreads();
    for (int o = 128; o > 0; o >>= 1) { if (tid < o) red[tid] += red[tid + o]; __syncthreads(); }
    if (tid == 0) d_casp[b] = red[0];
}

__global__ void k_zero() {
    int i = blockIdx.x * 256 + threadIdx.x;
    if (i < 2 * 2 * 300 * 256) ((float*)d_hstate)[i] = 0.f;
    if (i < 2 * 300 * 256) ((float*)d_cstate)[i] = 0.f;
}

// ---------------- input-gate GEMM with fused embedding gather ----------------
// Rows r = s*256 + b. Output layout: d_Gpre[dir][((s*1200 + n)*256 + b)]
__global__ __launch_bounds__(256) void k_gemm_in(const int* __restrict__ text,
                                                 const float* __restrict__ embed,
                                                 const float* __restrict__ fb,
                                                 const float* __restrict__ bb) {
    int dir = blockIdx.z;
    const float* wT = d_wihT[dir];
    const float* bias = dir ? bb : fb;
    float* C = d_Gpre + (size_t)dir * 65536 * 1200;

    __shared__ float As[8][128];
    __shared__ float Bs[8][128];
    __shared__ float Cs[8][128];
    int tid = threadIdx.x;
    int m0 = blockIdx.y * 128, n0 = blockIdx.x * 128;
    int s = m0 >> 8;
    int b0 = m0 & 255;
    int tx = tid & 15, ty = tid >> 4;

    float acc[8][8];
    #pragma unroll
    for (int i = 0; i < 8; i++)
        #pragma unroll
        for (int j = 0; j < 8; j++) acc[i][j] = 0.f;

    int am = tid >> 1;
    int ak4 = (tid & 1) * 4;
    int tok = text[(b0 + am) * SN + s];
    const float* aptr = embed + (size_t)tok * 300;
    int bn = (tid & 31) * 4;
    int bk = tid >> 5;
    bool bnval = (n0 + bn + 3) < 1200;

    for (int k0 = 0; k0 < 304; k0 += 8) {
        float4 av = make_float4(0.f, 0.f, 0.f, 0.f);
        int ka = k0 + ak4;
        if (ka <= 296) av = *(const float4*)(aptr + ka);
        As[ak4 + 0][am] = av.x;
        As[ak4 + 1][am] = av.y;
        As[ak4 + 2][am] = av.z;
        As[ak4 + 3][am] = av.w;

        float4 bv = make_float4(0.f, 0.f, 0.f, 0.f);
        int kb = k0 + bk;
        if (kb < 300 && bnval) bv = *(const float4*)(wT + (size_t)kb * 1200 + n0 + bn);
        *(float4*)&Bs[bk][bn] = bv;
        __syncthreads();

        #pragma unroll
        for (int kk = 0; kk < 8; kk++) {
            float a[8], bf[8];
            *(float4*)(a)      = *(const float4*)&As[kk][ty * 8];
            *(float4*)(a + 4)  = *(const float4*)&As[kk][ty * 8 + 4];
            *(float4*)(bf)     = *(const float4*)&Bs[kk][tx * 8];
            *(float4*)(bf + 4) = *(const float4*)&Bs[kk][tx * 8 + 4];
            #pragma unroll
            for (int i = 0; i < 8; i++)
                #pragma unroll
                for (int j = 0; j < 8; j++) acc[i][j] += a[i] * bf[j];
        }
        __syncthreads();
    }

    int jr = tid >> 5;
    int col4 = (tid & 31) * 4;
    #pragma unroll 1
    for (int c = 0; c < 16; c++) {
        if (tx == c) {
            #pragma unroll
            for (int j = 0; j < 8; j++) {
                int n = n0 + c * 8 + j;
                float bv = (n < 1200) ? bias[n] : 0.f;
                #pragma unroll
                for (int i = 0; i < 8; i++) Cs[j][ty * 8 + i] = acc[i][j] + bv;
            }
        }
        __syncthreads();
        int n = n0 + c * 8 + jr;
        if (n < 1200)
            *(float4*)&C[((size_t)s * 1200 + n) * 256 + b0 + col4] = *(const float4*)&Cs[jr][col4];
        __syncthreads();
    }
}

// ---------------- one LSTM timestep, both directions ----------------
// Grid = (30 ublocks, 2 bhalf, 2 dir) = 120 blocks (single wave).
// Block = 320 threads: warp = u (10 of them), lane = 4-batch group of 128 b.
__global__ __launch_bounds__(320) void k_step(int step) {
    int dir = blockIdx.z;
    int t = dir ? (SN - 1 - step) : step;
    const float* hprev = d_hstate[dir][step & 1];
    float* hnext = d_hstate[dir][(step + 1) & 1];
    float* cst = d_cstate[dir];
    const float* gpre = d_Gpre + (size_t)dir * 65536 * 1200;  // [t][n][b]

    int ub = blockIdx.x;
    int b0 = blockIdx.y * 128;
    int tid = threadIdx.x;
    int cg = tid >> 5;   // warp = u-offset 0..9
    int bg = tid & 31;   // 4-batch group
    int u = ub * UB + cg;
    int b = b0 + bg * 4;

    extern __shared__ float smem[];
    float* Ws = smem;           // [300][40]
    float* Hs = smem + 12000;   // [2][KC][128]

    // stage pre-rearranged W tile: contiguous 48 KB, coalesced
    {
        const float4* src = (const float4*)d_wstep[dir][ub];
        #pragma unroll
        for (int i = 0; i < 10; i++) {
            int idx = tid + i * 320;
            if (idx < 3000) ((float4*)Ws)[idx] = src[idx];
        }
    }

    // acc init from precomputed input gates (coalesced float4)
    float acc[4][4];  // [batch j][gate g]
    {
        const float* gp = gpre + (size_t)t * 1200 * 256;
        #pragma unroll
        for (int g = 0; g < 4; g++) {
            float4 v = *(const float4*)&gp[(size_t)(g * 300 + u) * 256 + b];
            acc[0][g] = v.x; acc[1][g] = v.y; acc[2][g] = v.z; acc[3][g] = v.w;
        }
    }

    // h chunk 0 -> shared (960 float4s)
    #pragma unroll
    for (int i = 0; i < 3; i++) {
        int idx = tid + i * 320;
        if (idx < 960)
            *(float4*)&Hs[(idx >> 5) * 128 + (idx & 31) * 4] =
                *(const float4*)&hprev[(idx >> 5) * 256 + b0 + (idx & 31) * 4];
    }
    __syncthreads();

    #pragma unroll 1
    for (int c = 0; c < 10; c++) {
        const float* hsc = Hs + (c & 1) * KC * 128;
        float4 pf[3];
        if (c < 9) {
            int kb = (c + 1) * KC;
            #pragma unroll
            for (int i = 0; i < 3; i++) {
                int idx = tid + i * 320;
                if (idx < 960)
                    pf[i] = *(const float4*)&hprev[(size_t)(kb + (idx >> 5)) * 256 + b0 + (idx & 31) * 4];
            }
        }
        const float* wbase = Ws + c * KC * 40 + cg * 4;
        #pragma unroll
        for (int kk = 0; kk < KC; kk++) {
            float4 hv = *(const float4*)&hsc[kk * 128 + bg * 4];
            float4 wv = *(const float4*)&wbase[kk * 40];
            acc[0][0] += hv.x * wv.x; acc[0][1] += hv.x * wv.y; acc[0][2] += hv.x * wv.z; acc[0][3] += hv.x * wv.w;
            acc[1][0] += hv.y * wv.x; acc[1][1] += hv.y * wv.y; acc[1][2] += hv.y * wv.z; acc[1][3] += hv.y * wv.w;
            acc[2][0] += hv.z * wv.x; acc[2][1] += hv.z * wv.y; acc[2][2] += hv.z * wv.z; acc[2][3] += hv.z * wv.w;
            acc[3][0] += hv.w * wv.x; acc[3][1] += hv.w * wv.y; acc[3][2] += hv.w * wv.z; acc[3][3] += hv.w * wv.w;
        }
        if (c < 9) {
            float* hsn = Hs + ((c + 1) & 1) * KC * 128;
            #pragma unroll
            for (int i = 0; i < 3; i++) {
                int idx = tid + i * 320;
                if (idx < 960)
                    *(float4*)&hsn[(idx >> 5) * 128 + (idx & 31) * 4] = pf[i];
            }
            __syncthreads();
        }
    }

    {
        float4 cv = *(const float4*)&cst[u * 256 + b];
        float cc[4] = {cv.x, cv.y, cv.z, cv.w};
        float hh[4];
        float tt = (float)t;
        #pragma unroll
        for (int j = 0; j < 4; j++) {
            float ig = sigf(acc[j][0]);
            float fg = sigf(acc[j][1]);
            float gg = tanhf(acc[j][2]);
            float og = sigf(acc[j][3]);
            float c2 = fg * cc[j] + ig * gg;
            cc[j] = c2;
            hh[j] = og * tanhf(c2);
            int bj = b + j;
            float llv = d_llen[bj], alv = d_alen[bj], Mv = d_mlen[bj];
            float w;
            if (tt < llv) w = 1.f - (llv - tt) / Mv;
            else if (tt < llv + alv) w = 1.f;
            else if (tt < Mv) w = 1.f - (tt - llv - alv + 1.f) / Mv;
            else w = 0.f;
            d_mem[((size_t)bj * SN + t) * DN + dir * 300 + u] = hh[j] * w;
        }
        *(float4*)&cst[u * 256 + b] = make_float4(cc[0], cc[1], cc[2], cc[3]);
        *(float4*)&hnext[u * 256 + b] = make_float4(hh[0], hh[1], hh[2], hh[3]);
    }
}

// ---------------- fill u column + gm = mem . attn_w[0:601]  ----------------
__global__ void k_gm(const float* __restrict__ aw) {
    int warp = threadIdx.x >> 5, lane = threadIdx.x & 31;
    int r = blockIdx.x * 8 + warp;
    int b = r >> 8, s = r & 255;
    float llv = d_llen[b], alv = d_alen[b], Mv = d_mlen[b];
    float ss = (float)s;
    float uu;
    if (ss < llv) uu = ss - llv;
    else if (ss < llv + alv) uu = 0.f;
    else if (ss < Mv) uu = ss - llv - alv + 1.f;
    else uu = 1.f;

    float* mrow = d_mem + (size_t)r * DN;
    float part = 0.f;
    for (int d = lane; d < DN; d += 32) {
        float v;
        if (d == 600) { v = uu; mrow[600] = uu; }
        else v = mrow[d];
        part += v * aw[d];
    }
    #pragma unroll
    for (int o = 16; o > 0; o >>= 1) part += __shfl_down_sync(0xffffffffu, part, o);
    if (lane == 0) d_gmT[s * BN + b] = part;
}

// ---------------- attention layer pieces ----------------
__global__ void k_gofs(const float* __restrict__ aw, const float* __restrict__ ab) {
    int b = blockIdx.x, tid = threadIdx.x;  // 128
    __shared__ float red[128];
    float p = 0.f;
    for (int k = tid; k < EN; k += 128) p += d_et[b * EN + k] * aw[601 + k];
    red[tid] = p;
    __syncthreads();
    for (int o = 64; o > 0; o >>= 1) { if (tid < o) red[tid] += red[tid + o]; __syncthreads(); }
    if (tid == 0) d_gofs[b] = red[0] + d_casp[b] + ab[0];
}

__global__ void k_softmax() {
    int s = blockIdx.x, b = threadIdx.x;
    __shared__ float red[256];
    float g = d_gmT[s * BN + b] + d_gofs[b];
    red[b] = g;
    __syncthreads();
    for (int o = 128; o > 0; o >>= 1) { if (b < o) red[b] = fmaxf(red[b], red[b + o]); __syncthreads(); }
    float mx = red[0];
    __syncthreads();
    float e = expf(g - mx);
    red[b] = e;
    __syncthreads();
    for (int o = 128; o > 0; o >>= 1) { if (b < o) red[b] += red[b + o]; __syncthreads(); }
    d_alphaT[s * BN + b] = e / red[0];
}

__global__ void k_isum() {
    int b = blockIdx.x, tid = threadIdx.x;  // 256
    __shared__ float al[256];
    al[tid] = d_alphaT[tid * BN + b];
    __syncthreads();
    float a0 = 0.f, a1 = 0.f, a2 = 0.f;
    int d0 = tid, d1 = tid + 256, d2 = tid + 512;
    bool v2 = d2 < DN;
    int d2c = v2 ? d2 : 600;
    const float* mb = d_mem + (size_t)b * SN * DN;
    #pragma unroll 4
    for (int s = 0; s < SN; s++) {
        float a = al[s];
        const float* mr = mb + (size_t)s * DN;
        a0 += a * mr[d0];
        a1 += a * mr[d1];
        a2 += a * mr[d2c];
    }
    d_ivec[b * DN + d0] = a0;
    d_ivec[b * DN + d1] = a1;
    if (v2) d_ivec[b * DN + d2] = a2;
}

// 4 batch elements per block: W rows loaded once, reused x4
__global__ __launch_bounds__(256) void k_gru(const float* __restrict__ bih,
                                             const float* __restrict__ bhh) {
    int b0 = blockIdx.x * 4;
    int tid = threadIdx.x;  // 256
    __shared__ float si[4][608];
    __shared__ float se[4][304];
    __shared__ float gi[4][904];
    __shared__ float gh[4][904];
    #pragma unroll
    for (int bb = 0; bb < 4; bb++) {
        for (int k = tid; k < DN; k += 256) si[bb][k] = d_ivec[(b0 + bb) * DN + k];
        for (int k = tid; k < EN; k += 256) se[bb][k] = d_et[(b0 + bb) * EN + k];
    }
    __syncthreads();

    int r0 = tid, r1 = tid + 256, r2 = tid + 512, r3 = tid + 768;
    bool v3 = r3 < 900;
    int r3c = v3 ? r3 : 899;

    float acc[4][4];
    #pragma unroll
    for (int bb = 0; bb < 4; bb++) {
        acc[bb][0] = bih[r0]; acc[bb][1] = bih[r1]; acc[bb][2] = bih[r2]; acc[bb][3] = bih[r3c];
    }
    for (int k = 0; k < DN; k++) {
        const float* w = d_gwihT + (size_t)k * 900;
        float w0 = w[r0], w1 = w[r1], w2 = w[r2], w3 = w[r3c];
        #pragma unroll
        for (int bb = 0; bb < 4; bb++) {
            float v = si[bb][k];
            acc[bb][0] += v * w0; acc[bb][1] += v * w1; acc[bb][2] += v * w2; acc[bb][3] += v * w3;
        }
    }
    #pragma unroll
    for (int bb = 0; bb < 4; bb++) {
        gi[bb][r0] = acc[bb][0]; gi[bb][r1] = acc[bb][1]; gi[bb][r2] = acc[bb][2];
        if (v3) gi[bb][r3] = acc[bb][3];
    }

    #pragma unroll
    for (int bb = 0; bb < 4; bb++) {
        acc[bb][0] = bhh[r0]; acc[bb][1] = bhh[r1]; acc[bb][2] = bhh[r2]; acc[bb][3] = bhh[r3c];
    }
    for (int k = 0; k < EN; k++) {
        const float* w = d_gwhhT + (size_t)k * 900;
        float w0 = w[r0], w1 = w[r1], w2 = w[r2], w3 = w[r3c];
        #pragma unroll
        for (int bb = 0; bb < 4; bb++) {
            float v = se[bb][k];
            acc[bb][0] += v * w0; acc[bb][1] += v * w1; acc[bb][2] += v * w2; acc[bb][3] += v * w3;
        }
    }
    #pragma unroll
    for (int bb = 0; bb < 4; bb++) {
        gh[bb][r0] = acc[bb][0]; gh[bb][r1] = acc[bb][1]; gh[bb][r2] = acc[bb][2];
        if (v3) gh[bb][r3] = acc[bb][3];
    }
    __syncthreads();

    for (int e = tid; e < EN; e += 256) {
        #pragma unroll
        for (int bb = 0; bb < 4; bb++) {
            float rr = sigf(gi[bb][e] + gh[bb][e]);
            float zz = sigf(gi[bb][300 + e] + gh[bb][300 + e]);
            float nn = tanhf(gi[bb][600 + e] + rr * gh[bb][600 + e]);
            d_et[(b0 + bb) * EN + e] = (1.f - zz) * nn + zz * se[bb][e];
        }
    }
}

__global__ void k_dense(const float* __restrict__ dw, const float* __restrict__ db,
                        float* __restrict__ out) {
    int b = blockIdx.x;
    int p = threadIdx.x >> 5;
    int lane = threadIdx.x & 31;
    if (p < POLN) {
        float s = 0.f;
        for (int k = lane; k < EN; k += 32) s += d_et[b * EN + k] * dw[p * EN + k];
        #pragma unroll
        for (int o = 16; o > 0; o >>= 1) s += __shfl_down_sync(0xffffffffu, s, o);
        if (lane == 0) out[b * POLN + p] = s + db[p];
    }
}

// ---------------- launcher ----------------
extern "C" void kernel_launch(void* const* d_in, const int* in_sizes, int n_in,
                              void* d_out, int out_size) {
    const int* text = (const int*)d_in[0];
    const int* aspect = (const int*)d_in[1];
    const int* left = (const int*)d_in[2];
    const float* embed = (const float*)d_in[3];
    const float* fwih = (const float*)d_in[4];
    const float* fwhh = (const float*)d_in[5];
    const float* fb = (const float*)d_in[6];
    const float* bwih = (const float*)d_in[7];
    const float* bwhh = (const float*)d_in[8];
    const float* bb = (const float*)d_in[9];
    const float* aw = (const float*)d_in[10];
    const float* ab = (const float*)d_in[11];
    const float* gwih = (const float*)d_in[12];
    const float* gwhh = (const float*)d_in[13];
    const float* gbih = (const float*)d_in[14];
    const float* gbhh = (const float*)d_in[15];
    const float* dw = (const float*)d_in[16];
    const float* db = (const float*)d_in[17];
    float* out = (float*)d_out;

    const int step_smem = (12000 + 2 * KC * 128) * 4;  // 78720 B
    cudaFuncSetAttribute(k_step, cudaFuncAttributeMaxDynamicSharedMemorySize, step_smem);

    k_transpose_all<<<dim3(19, 38, 6), dim3(32, 8)>>>(fwih, fwhh, bwih, bwhh, gwih, gwhh);
    k_wstep<<<dim3(NUB, 2), 256>>>();
    k_prep_b<<<256, 256>>>(text, left, aspect, embed, aw);
    k_zero<<<1200, 256>>>();
    k_gemm_in<<<dim3(10, 512, 2), 256>>>(text, embed, fb, bb);
    for (int st = 0; st < SN; st++)
        k_step<<<dim3(NUB, 2, 2), 320, step_smem>>>(st);
    k_gm<<<8192, 256>>>(aw);
    for (int l = 0; l < 4; l++) {
        k_gofs<<<256, 128>>>(aw, ab);
        k_softmax<<<256, 256>>>();
        k_isum<<<256, 256>>>();
        k_gru<<<64, 256>>>(gbih, gbhh);
    }
    k_dense<<<256, 96>>>(dw, db, out);
}

// round 6
// speedup vs baseline: 1.3791x; 1.0901x over previous
#include <cuda_runtime.h>
#include <math.h>

#define BN 256
#define SN 256
#define EN 300
#define HN 300
#define G4 1200
#define DN 601
#define AN 16
#define POLN 3
#define KC 30
#define UB 10     // u-units per step block
#define NUB 30    // number of u-blocks (30*10 = 300)

// ---------------- static device scratch (no allocations allowed) ----------------
__device__ float d_wihT[2][300 * 1200];      // input weights, k-major
__device__ float d_whhT[2][300 * 1200];      // recurrent weights, k-major
__device__ float d_wstep[2][NUB][300 * 40];  // step weights: [dir][ub][k][uoff*4+g]
__device__ float d_gwihT[601 * 900];         // GRU W_ih^T  (k-major)
__device__ float d_gwhhT[300 * 900];         // GRU W_hh^T  (k-major)
__device__ float d_Gpre[2 * 65536 * 1200];   // input gates, layout [dir][t][n][b]
__device__ float d_mem[65536 * 601];         // location-weighted memory [b][s][d]
__device__ float d_hstate[2][2][300 * 256];  // [dir][parity][u][b]
__device__ float d_gmT[65536];               // [s][b]
__device__ float d_alphaT[65536];            // [s][b]
__device__ float d_gofs[256];
__device__ float d_asp[256 * 300];
__device__ float d_casp[256];
__device__ float d_et[256 * 300];
__device__ float d_ivec[256 * 601];
__device__ float d_llen[256], d_alen[256], d_mlen[256];
__device__ unsigned d_barcnt[4];
__device__ unsigned d_bargen[4];

__device__ __forceinline__ float sigf(float x) { return 1.f / (1.f + expf(-x)); }

// ---------------- weight transposes ----------------
__global__ void k_transpose_all(const float* __restrict__ fwih, const float* __restrict__ fwhh,
                                const float* __restrict__ bwih, const float* __restrict__ bwhh,
                                const float* __restrict__ gwih, const float* __restrict__ gwhh) {
    int id = blockIdx.z;
    const float* src;
    float* dst;
    int R, C;
    switch (id) {
        case 0: src = fwih; dst = d_wihT[0]; R = 1200; C = 300; break;
        case 1: src = fwhh; dst = d_whhT[0]; R = 1200; C = 300; break;
        case 2: src = bwih; dst = d_wihT[1]; R = 1200; C = 300; break;
        case 3: src = bwhh; dst = d_whhT[1]; R = 1200; C = 300; break;
        case 4: src = gwih; dst = d_gwihT;   R = 900;  C = 601; break;
        default: src = gwhh; dst = d_gwhhT;  R = 900;  C = 300; break;
    }
    __shared__ float tile[32][33];
    int c0 = blockIdx.x * 32, r0 = blockIdx.y * 32;
    int x = threadIdx.x, y = threadIdx.y;  // 32 x 8
    #pragma unroll
    for (int i = 0; i < 32; i += 8) {
        int r = r0 + y + i, c = c0 + x;
        if (r < R && c < C) tile[y + i][x] = src[(size_t)r * C + c];
    }
    __syncthreads();
    #pragma unroll
    for (int i = 0; i < 32; i += 8) {
        int c = c0 + y + i, r = r0 + x;
        if (c < C && r < R) dst[(size_t)c * R + r] = tile[x][y + i];
    }
}

// build d_wstep from d_whhT (one block per (dir, ub))
__global__ void k_wstep() {
    int dir = blockIdx.y;
    int ub = blockIdx.x;
    const float* w = d_whhT[dir];
    float* dst = d_wstep[dir][ub];
    for (int i = threadIdx.x; i < 300 * 40; i += blockDim.x) {
        int k = i / 40;
        int col = i % 40;
        int uoff = col >> 2, g = col & 3;
        dst[i] = w[(size_t)k * 1200 + g * 300 + ub * UB + uoff];
    }
}

// ---------------- lengths / aspect vector / init ----------------
__global__ void k_prep_b(const int* __restrict__ text, const int* __restrict__ left,
                         const int* __restrict__ aspect, const float* __restrict__ embed,
                         const float* __restrict__ aw) {
    int b = blockIdx.x;
    int tid = threadIdx.x;  // 256
    __shared__ float red[256];
    __shared__ float s_alen;

    red[tid] = (text[b * SN + tid] != 0) ? 1.f : 0.f;
    __syncthreads();
    for (int o = 128; o > 0; o >>= 1) { if (tid < o) red[tid] += red[tid + o]; __syncthreads(); }
    if (tid == 0) d_mlen[b] = red[0];
    __syncthreads();

    red[tid] = (left[b * SN + tid] != 0) ? 1.f : 0.f;
    __syncthreads();
    for (int o = 128; o > 0; o >>= 1) { if (tid < o) red[tid] += red[tid + o]; __syncthreads(); }
    if (tid == 0) d_llen[b] = red[0];
    __syncthreads();

    red[tid] = (tid < AN && aspect[b * AN + tid] != 0) ? 1.f : 0.f;
    __syncthreads();
    for (int o = 128; o > 0; o >>= 1) { if (tid < o) red[tid] += red[tid + o]; __syncthreads(); }
    if (tid == 0) { s_alen = red[0]; d_alen[b] = red[0]; }
    __syncthreads();
    float alen = s_alen;

    float part = 0.f;
    for (int d = tid; d < EN; d += 256) {
        float s = 0.f;
        #pragma unroll
        for (int a = 0; a < AN; a++) {
            int tok = aspect[b * AN + a];
            s += embed[(size_t)tok * EN + d];
        }
        s /= alen;
        d_asp[b * EN + d] = s;
        d_et[b * EN + d] = 0.f;
        part += s * aw[901 + d];
    }
    red[tid] = part;
    __syncthreads();
    for (int o = 128; o > 0; o >>= 1) { if (tid < o) red[tid] += red[tid + o]; __syncthreads(); }
    if (tid == 0) d_casp[b] = red[0];
}

__global__ void k_zero() {
    int i = blockIdx.x * 256 + threadIdx.x;
    if (i < 2 * 2 * 300 * 256) ((float*)d_hstate)[i] = 0.f;
    if (i < 4) { d_barcnt[i] = 0; d_bargen[i] = 0; }
}

// ---------------- input-gate GEMM with fused embedding gather ----------------
// Rows r = s*256 + b. Output layout: d_Gpre[dir][((s*1200 + n)*256 + b)]
__global__ __launch_bounds__(256) void k_gemm_in(const int* __restrict__ text,
                                                 const float* __restrict__ embed,
                                                 const float* __restrict__ fb,
                                                 const float* __restrict__ bb) {
    int dir = blockIdx.z;
    const float* wT = d_wihT[dir];
    const float* bias = dir ? bb : fb;
    float* C = d_Gpre + (size_t)dir * 65536 * 1200;

    __shared__ float As[8][128];
    __shared__ float Bs[8][128];
    __shared__ float Cs[8][128];
    int tid = threadIdx.x;
    int m0 = blockIdx.y * 128, n0 = blockIdx.x * 128;
    int s = m0 >> 8;
    int b0 = m0 & 255;
    int tx = tid & 15, ty = tid >> 4;

    float acc[8][8];
    #pragma unroll
    for (int i = 0; i < 8; i++)
        #pragma unroll
        for (int j = 0; j < 8; j++) acc[i][j] = 0.f;

    int am = tid >> 1;
    int ak4 = (tid & 1) * 4;
    int tok = text[(b0 + am) * SN + s];
    const float* aptr = embed + (size_t)tok * 300;
    int bn = (tid & 31) * 4;
    int bk = tid >> 5;
    bool bnval = (n0 + bn + 3) < 1200;

    for (int k0 = 0; k0 < 304; k0 += 8) {
        float4 av = make_float4(0.f, 0.f, 0.f, 0.f);
        int ka = k0 + ak4;
        if (ka <= 296) av = *(const float4*)(aptr + ka);
        As[ak4 + 0][am] = av.x;
        As[ak4 + 1][am] = av.y;
        As[ak4 + 2][am] = av.z;
        As[ak4 + 3][am] = av.w;

        float4 bv = make_float4(0.f, 0.f, 0.f, 0.f);
        int kb = k0 + bk;
        if (kb < 300 && bnval) bv = *(const float4*)(wT + (size_t)kb * 1200 + n0 + bn);
        *(float4*)&Bs[bk][bn] = bv;
        __syncthreads();

        #pragma unroll
        for (int kk = 0; kk < 8; kk++) {
            float a[8], bf[8];
            *(float4*)(a)      = *(const float4*)&As[kk][ty * 8];
            *(float4*)(a + 4)  = *(const float4*)&As[kk][ty * 8 + 4];
            *(float4*)(bf)     = *(const float4*)&Bs[kk][tx * 8];
            *(float4*)(bf + 4) = *(const float4*)&Bs[kk][tx * 8 + 4];
            #pragma unroll
            for (int i = 0; i < 8; i++)
                #pragma unroll
                for (int j = 0; j < 8; j++) acc[i][j] += a[i] * bf[j];
        }
        __syncthreads();
    }

    int jr = tid >> 5;
    int col4 = (tid & 31) * 4;
    #pragma unroll 1
    for (int c = 0; c < 16; c++) {
        if (tx == c) {
            #pragma unroll
            for (int j = 0; j < 8; j++) {
                int n = n0 + c * 8 + j;
                float bv = (n < 1200) ? bias[n] : 0.f;
                #pragma unroll
                for (int i = 0; i < 8; i++) Cs[j][ty * 8 + i] = acc[i][j] + bv;
            }
        }
        __syncthreads();
        int n = n0 + c * 8 + jr;
        if (n < 1200)
            *(float4*)&C[((size_t)s * 1200 + n) * 256 + b0 + col4] = *(const float4*)&Cs[jr][col4];
        __syncthreads();
    }
}

// ---------------- persistent LSTM: all 256 timesteps in one launch ----------------
// Grid = (30 ublocks, 2 bhalf, 2 dir) = 120 blocks, all resident (single wave).
// Barrier cohort = 30 u-blocks sharing (dir, bhalf). Cell state lives in registers.
__global__ __launch_bounds__(320) void k_steps_all() {
    int dir = blockIdx.z;
    int bh = blockIdx.y;
    int grp = dir * 2 + bh;
    int ub = blockIdx.x;
    int b0 = bh * 128;
    int tid = threadIdx.x;
    int cg = tid >> 5;   // warp = u-offset 0..9
    int bg = tid & 31;   // 4-batch group
    int u = ub * UB + cg;
    int b = b0 + bg * 4;

    extern __shared__ float smem[];
    float* Ws = smem;           // [300][40]
    float* Hs = smem + 12000;   // [2][KC][128]

    // stage pre-rearranged W tile once for all 256 steps
    {
        const float4* src = (const float4*)d_wstep[dir][ub];
        #pragma unroll
        for (int i = 0; i < 10; i++) {
            int idx = tid + i * 320;
            if (idx < 3000) ((float4*)Ws)[idx] = src[idx];
        }
    }

    // per-b location params, resident in registers
    float llv[4], alv[4], Mv[4];
    #pragma unroll
    for (int j = 0; j < 4; j++) {
        llv[j] = d_llen[b + j];
        alv[j] = d_alen[b + j];
        Mv[j]  = d_mlen[b + j];
    }

    float cc[4] = {0.f, 0.f, 0.f, 0.f};  // cell state: registers across all steps
    const float* gpre = d_Gpre + (size_t)dir * 65536 * 1200;
    unsigned gen = 0;

    #pragma unroll 1
    for (int st = 0; st < SN; st++) {
        int t = dir ? (SN - 1 - st) : st;
        const float* hprev = d_hstate[dir][st & 1];
        float* hnext = d_hstate[dir][(st + 1) & 1];

        float acc[4][4];  // [batch j][gate g]
        {
            const float* gp = gpre + (size_t)t * 1200 * 256;
            #pragma unroll
            for (int g = 0; g < 4; g++) {
                float4 v = *(const float4*)&gp[(size_t)(g * 300 + u) * 256 + b];
                acc[0][g] = v.x; acc[1][g] = v.y; acc[2][g] = v.z; acc[3][g] = v.w;
            }
        }

        // h chunk 0 -> shared
        #pragma unroll
        for (int i = 0; i < 3; i++) {
            int idx = tid + i * 320;
            if (idx < 960)
                *(float4*)&Hs[(idx >> 5) * 128 + (idx & 31) * 4] =
                    *(const float4*)&hprev[(idx >> 5) * 256 + b0 + (idx & 31) * 4];
        }
        __syncthreads();

        #pragma unroll 1
        for (int c = 0; c < 10; c++) {
            const float* hsc = Hs + (c & 1) * KC * 128;
            float4 pf[3];
            if (c < 9) {
                int kb = (c + 1) * KC;
                #pragma unroll
                for (int i = 0; i < 3; i++) {
                    int idx = tid + i * 320;
                    if (idx < 960)
                        pf[i] = *(const float4*)&hprev[(size_t)(kb + (idx >> 5)) * 256 + b0 + (idx & 31) * 4];
                }
            }
            const float* wbase = Ws + c * KC * 40 + cg * 4;
            #pragma unroll
            for (int kk = 0; kk < KC; kk++) {
                float4 hv = *(const float4*)&hsc[kk * 128 + bg * 4];
                float4 wv = *(const float4*)&wbase[kk * 40];
                acc[0][0] += hv.x * wv.x; acc[0][1] += hv.x * wv.y; acc[0][2] += hv.x * wv.z; acc[0][3] += hv.x * wv.w;
                acc[1][0] += hv.y * wv.x; acc[1][1] += hv.y * wv.y; acc[1][2] += hv.y * wv.z; acc[1][3] += hv.y * wv.w;
                acc[2][0] += hv.z * wv.x; acc[2][1] += hv.z * wv.y; acc[2][2] += hv.z * wv.z; acc[2][3] += hv.z * wv.w;
                acc[3][0] += hv.w * wv.x; acc[3][1] += hv.w * wv.y; acc[3][2] += hv.w * wv.z; acc[3][3] += hv.w * wv.w;
            }
            if (c < 9) {
                float* hsn = Hs + ((c + 1) & 1) * KC * 128;
                #pragma unroll
                for (int i = 0; i < 3; i++) {
                    int idx = tid + i * 320;
                    if (idx < 960)
                        *(float4*)&hsn[(idx >> 5) * 128 + (idx & 31) * 4] = pf[i];
                }
                __syncthreads();
            }
        }

        {
            float hh[4];
            float tt = (float)t;
            #pragma unroll
            for (int j = 0; j < 4; j++) {
                float ig = sigf(acc[j][0]);
                float fg = sigf(acc[j][1]);
                float gg = tanhf(acc[j][2]);
                float og = sigf(acc[j][3]);
                float c2 = fg * cc[j] + ig * gg;
                cc[j] = c2;
                hh[j] = og * tanhf(c2);
                float w;
                if (tt < llv[j]) w = 1.f - (llv[j] - tt) / Mv[j];
                else if (tt < llv[j] + alv[j]) w = 1.f;
                else if (tt < Mv[j]) w = 1.f - (tt - llv[j] - alv[j] + 1.f) / Mv[j];
                else w = 0.f;
                d_mem[((size_t)(b + j) * SN + t) * DN + dir * 300 + u] = hh[j] * w;
            }
            *(float4*)&hnext[u * 256 + b] = make_float4(hh[0], hh[1], hh[2], hh[3]);
        }

        // 30-block group barrier (skip after last step)
        if (st < SN - 1) {
            gen++;
            __syncthreads();
            if (tid == 0) {
                __threadfence();
                unsigned a = atomicAdd(&d_barcnt[grp], 1);
                if (a == NUB - 1) {
                    d_barcnt[grp] = 0;
                    __threadfence();
                    atomicAdd(&d_bargen[grp], 1);
                } else {
                    while (atomicAdd(&d_bargen[grp], 0) < gen) { __nanosleep(60); }
                }
                __threadfence();
            }
            __syncthreads();
        }
    }
}

// ---------------- fill u column + gm = mem . attn_w[0:601]  ----------------
__global__ void k_gm(const float* __restrict__ aw) {
    int warp = threadIdx.x >> 5, lane = threadIdx.x & 31;
    int r = blockIdx.x * 8 + warp;
    int b = r >> 8, s = r & 255;
    float llv = d_llen[b], alv = d_alen[b], Mv = d_mlen[b];
    float ss = (float)s;
    float uu;
    if (ss < llv) uu = ss - llv;
    else if (ss < llv + alv) uu = 0.f;
    else if (ss < Mv) uu = ss - llv - alv + 1.f;
    else uu = 1.f;

    float* mrow = d_mem + (size_t)r * DN;
    float part = 0.f;
    for (int d = lane; d < DN; d += 32) {
        float v;
        if (d == 600) { v = uu; mrow[600] = uu; }
        else v = mrow[d];
        part += v * aw[d];
    }
    #pragma unroll
    for (int o = 16; o > 0; o >>= 1) part += __shfl_down_sync(0xffffffffu, part, o);
    if (lane == 0) d_gmT[s * BN + b] = part;
}

// ---------------- attention layer pieces ----------------
__global__ void k_gofs(const float* __restrict__ aw, const float* __restrict__ ab) {
    int b = blockIdx.x, tid = threadIdx.x;  // 128
    __shared__ float red[128];
    float p = 0.f;
    for (int k = tid; k < EN; k += 128) p += d_et[b * EN + k] * aw[601 + k];
    red[tid] = p;
    __syncthreads();
    for (int o = 64; o > 0; o >>= 1) { if (tid < o) red[tid] += red[tid + o]; __syncthreads(); }
    if (tid == 0) d_gofs[b] = red[0] + d_casp[b] + ab[0];
}

__global__ void k_softmax() {
    int s = blockIdx.x, b = threadIdx.x;
    __shared__ float red[256];
    float g = d_gmT[s * BN + b] + d_gofs[b];
    red[b] = g;
    __syncthreads();
    for (int o = 128; o > 0; o >>= 1) { if (b < o) red[b] = fmaxf(red[b], red[b + o]); __syncthreads(); }
    float mx = red[0];
    __syncthreads();
    float e = expf(g - mx);
    red[b] = e;
    __syncthreads();
    for (int o = 128; o > 0; o >>= 1) { if (b < o) red[b] += red[b + o]; __syncthreads(); }
    d_alphaT[s * BN + b] = e / red[0];
}

__global__ void k_isum() {
    int b = blockIdx.x, tid = threadIdx.x;  // 256
    __shared__ float al[256];
    al[tid] = d_alphaT[tid * BN + b];
    __syncthreads();
    float a0 = 0.f, a1 = 0.f, a2 = 0.f;
    int d0 = tid, d1 = tid + 256, d2 = tid + 512;
    bool v2 = d2 < DN;
    int d2c = v2 ? d2 : 600;
    const float* mb = d_mem + (size_t)b * SN * DN;
    #pragma unroll 4
    for (int s = 0; s < SN; s++) {
        float a = al[s];
        const float* mr = mb + (size_t)s * DN;
        a0 += a * mr[d0];
        a1 += a * mr[d1];
        a2 += a * mr[d2c];
    }
    d_ivec[b * DN + d0] = a0;
    d_ivec[b * DN + d1] = a1;
    if (v2) d_ivec[b * DN + d2] = a2;
}

// 4 batch elements per block: W rows loaded once, reused x4
__global__ __launch_bounds__(256) void k_gru(const float* __restrict__ bih,
                                             const float* __restrict__ bhh) {
    int b0 = blockIdx.x * 4;
    int tid = threadIdx.x;  // 256
    __shared__ float si[4][608];
    __shared__ float se[4][304];
    __shared__ float gi[4][904];
    __shared__ float gh[4][904];
    #pragma unroll
    for (int bb = 0; bb < 4; bb++) {
        for (int k = tid; k < DN; k += 256) si[bb][k] = d_ivec[(b0 + bb) * DN + k];
        for (int k = tid; k < EN; k += 256) se[bb][k] = d_et[(b0 + bb) * EN + k];
    }
    __syncthreads();

    int r0 = tid, r1 = tid + 256, r2 = tid + 512, r3 = tid + 768;
    bool v3 = r3 < 900;
    int r3c = v3 ? r3 : 899;

    float acc[4][4];
    #pragma unroll
    for (int bb = 0; bb < 4; bb++) {
        acc[bb][0] = bih[r0]; acc[bb][1] = bih[r1]; acc[bb][2] = bih[r2]; acc[bb][3] = bih[r3c];
    }
    for (int k = 0; k < DN; k++) {
        const float* w = d_gwihT + (size_t)k * 900;
        float w0 = w[r0], w1 = w[r1], w2 = w[r2], w3 = w[r3c];
        #pragma unroll
        for (int bb = 0; bb < 4; bb++) {
            float v = si[bb][k];
            acc[bb][0] += v * w0; acc[bb][1] += v * w1; acc[bb][2] += v * w2; acc[bb][3] += v * w3;
        }
    }
    #pragma unroll
    for (int bb = 0; bb < 4; bb++) {
        gi[bb][r0] = acc[bb][0]; gi[bb][r1] = acc[bb][1]; gi[bb][r2] = acc[bb][2];
        if (v3) gi[bb][r3] = acc[bb][3];
    }

    #pragma unroll
    for (int bb = 0; bb < 4; bb++) {
        acc[bb][0] = bhh[r0]; acc[bb][1] = bhh[r1]; acc[bb][2] = bhh[r2]; acc[bb][3] = bhh[r3c];
    }
    for (int k = 0; k < EN; k++) {
        const float* w = d_gwhhT + (size_t)k * 900;
        float w0 = w[r0], w1 = w[r1], w2 = w[r2], w3 = w[r3c];
        #pragma unroll
        for (int bb = 0; bb < 4; bb++) {
            float v = se[bb][k];
            acc[bb][0] += v * w0; acc[bb][1] += v * w1; acc[bb][2] += v * w2; acc[bb][3] += v * w3;
        }
    }
    #pragma unroll
    for (int bb = 0; bb < 4; bb++) {
        gh[bb][r0] = acc[bb][0]; gh[bb][r1] = acc[bb][1]; gh[bb][r2] = acc[bb][2];
        if (v3) gh[bb][r3] = acc[bb][3];
    }
    __syncthreads();

    for (int e = tid; e < EN; e += 256) {
        #pragma unroll
        for (int bb = 0; bb < 4; bb++) {
            float rr = sigf(gi[bb][e] + gh[bb][e]);
            float zz = sigf(gi[bb][300 + e] + gh[bb][300 + e]);
            float nn = tanhf(gi[bb][600 + e] + rr * gh[bb][600 + e]);
            d_et[(b0 + bb) * EN + e] = (1.f - zz) * nn + zz * se[bb][e];
        }
    }
}

__global__ void k_dense(const float* __restrict__ dw, const float* __restrict__ db,
                        float* __restrict__ out) {
    int b = blockIdx.x;
    int p = threadIdx.x >> 5;
    int lane = threadIdx.x & 31;
    if (p < POLN) {
        float s = 0.f;
        for (int k = lane; k < EN; k += 32) s += d_et[b * EN + k] * dw[p * EN + k];
        #pragma unroll
        for (int o = 16; o > 0; o >>= 1) s += __shfl_down_sync(0xffffffffu, s, o);
        if (lane == 0) out[b * POLN + p] = s + db[p];
    }
}

// ---------------- launcher ----------------
extern "C" void kernel_launch(void* const* d_in, const int* in_sizes, int n_in,
                              void* d_out, int out_size) {
    const int* text = (const int*)d_in[0];
    const int* aspect = (const int*)d_in[1];
    const int* left = (const int*)d_in[2];
    const float* embed = (const float*)d_in[3];
    const float* fwih = (const float*)d_in[4];
    const float* fwhh = (const float*)d_in[5];
    const float* fb = (const float*)d_in[6];
    const float* bwih = (const float*)d_in[7];
    const float* bwhh = (const float*)d_in[8];
    const float* bb = (const float*)d_in[9];
    const float* aw = (const float*)d_in[10];
    const float* ab = (const float*)d_in[11];
    const float* gwih = (const float*)d_in[12];
    const float* gwhh = (const float*)d_in[13];
    const float* gbih = (const float*)d_in[14];
    const float* gbhh = (const float*)d_in[15];
    const float* dw = (const float*)d_in[16];
    const float* db = (const float*)d_in[17];
    float* out = (float*)d_out;

    const int step_smem = (12000 + 2 * KC * 128) * 4;  // 78720 B
    cudaFuncSetAttribute(k_steps_all, cudaFuncAttributeMaxDynamicSharedMemorySize, step_smem);

    k_transpose_all<<<dim3(19, 38, 6), dim3(32, 8)>>>(fwih, fwhh, bwih, bwhh, gwih, gwhh);
    k_wstep<<<dim3(NUB, 2), 256>>>();
    k_prep_b<<<256, 256>>>(text, left, aspect, embed, aw);
    k_zero<<<1200, 256>>>();
    k_gemm_in<<<dim3(10, 512, 2), 256>>>(text, embed, fb, bb);
    k_steps_all<<<dim3(NUB, 2, 2), 320, step_smem>>>();
    k_gm<<<8192, 256>>>(aw);
    for (int l = 0; l < 4; l++) {
        k_gofs<<<256, 128>>>(aw, ab);
        k_softmax<<<256, 256>>>();
        k_isum<<<256, 256>>>();
        k_gru<<<64, 256>>>(gbih, gbhh);
    }
    k_dense<<<256, 96>>>(dw, db, out);
}

// round 7
// speedup vs baseline: 1.6011x; 1.1610x over previous
#include <cuda_runtime.h>
#include <math.h>

#define BN 256
#define SN 256
#define EN 300
#define HN 300
#define G4 1200
#define DN 601
#define AN 16
#define POLN 3
#define KC 30
#define UB 10     // u-units per step block
#define NUB 30    // number of u-blocks (30*10 = 300)
#define VN 32000

// ---------------- static device scratch (no allocations allowed) ----------------
__device__ float d_wihT[2][300 * 1200];      // input weights, k-major
__device__ float d_whhT[2][300 * 1200];      // recurrent weights, k-major
__device__ float d_wstep[2][NUB][300 * 40];  // step weights: [dir][ub][k][uoff*4+g]
__device__ float d_P[2][VN * 1200];          // vocab projection: embed@W_ih^T + bias
__device__ float d_gwihT[601 * 900];         // GRU W_ih^T  (k-major)
__device__ float d_gwhhT[300 * 900];         // GRU W_hh^T  (k-major)
__device__ float d_Gpre[2 * 65536 * 1200];   // input gates, layout [dir][t][n][b]
__device__ float d_mem[65536 * 601];         // location-weighted memory [b][s][d]
__device__ float d_hstate[2][2][300 * 256];  // [dir][parity][u][b]
__device__ float d_gmT[65536];               // [s][b]
__device__ float d_alphaT[65536];            // [s][b]
__device__ float d_gofs[256];
__device__ float d_asp[256 * 300];
__device__ float d_casp[256];
__device__ float d_et[256 * 300];
__device__ float d_ivec[256 * 601];
__device__ float d_llen[256], d_alen[256], d_mlen[256];
__device__ unsigned d_barcnt[4];
__device__ unsigned d_bargen[4];

__device__ __forceinline__ float sigf(float x) { return 1.f / (1.f + expf(-x)); }

// ---------------- weight transposes ----------------
__global__ void k_transpose_all(const float* __restrict__ fwih, const float* __restrict__ fwhh,
                                const float* __restrict__ bwih, const float* __restrict__ bwhh,
                                const float* __restrict__ gwih, const float* __restrict__ gwhh) {
    int id = blockIdx.z;
    const float* src;
    float* dst;
    int R, C;
    switch (id) {
        case 0: src = fwih; dst = d_wihT[0]; R = 1200; C = 300; break;
        case 1: src = fwhh; dst = d_whhT[0]; R = 1200; C = 300; break;
        case 2: src = bwih; dst = d_wihT[1]; R = 1200; C = 300; break;
        case 3: src = bwhh; dst = d_whhT[1]; R = 1200; C = 300; break;
        case 4: src = gwih; dst = d_gwihT;   R = 900;  C = 601; break;
        default: src = gwhh; dst = d_gwhhT;  R = 900;  C = 300; break;
    }
    __shared__ float tile[32][33];
    int c0 = blockIdx.x * 32, r0 = blockIdx.y * 32;
    int x = threadIdx.x, y = threadIdx.y;  // 32 x 8
    #pragma unroll
    for (int i = 0; i < 32; i += 8) {
        int r = r0 + y + i, c = c0 + x;
        if (r < R && c < C) tile[y + i][x] = src[(size_t)r * C + c];
    }
    __syncthreads();
    #pragma unroll
    for (int i = 0; i < 32; i += 8) {
        int c = c0 + y + i, r = r0 + x;
        if (c < C && r < R) dst[(size_t)c * R + r] = tile[x][y + i];
    }
}

// build d_wstep from d_whhT (one block per (dir, ub))
__global__ void k_wstep() {
    int dir = blockIdx.y;
    int ub = blockIdx.x;
    const float* w = d_whhT[dir];
    float* dst = d_wstep[dir][ub];
    for (int i = threadIdx.x; i < 300 * 40; i += blockDim.x) {
        int k = i / 40;
        int col = i % 40;
        int uoff = col >> 2, g = col & 3;
        dst[i] = w[(size_t)k * 1200 + g * 300 + ub * UB + uoff];
    }
}

// ---------------- lengths / aspect vector / init ----------------
__global__ void k_prep_b(const int* __restrict__ text, const int* __restrict__ left,
                         const int* __restrict__ aspect, const float* __restrict__ embed,
                         const float* __restrict__ aw) {
    int b = blockIdx.x;
    int tid = threadIdx.x;  // 256
    __shared__ float red[256];
    __shared__ float s_alen;

    red[tid] = (text[b * SN + tid] != 0) ? 1.f : 0.f;
    __syncthreads();
    for (int o = 128; o > 0; o >>= 1) { if (tid < o) red[tid] += red[tid + o]; __syncthreads(); }
    if (tid == 0) d_mlen[b] = red[0];
    __syncthreads();

    red[tid] = (left[b * SN + tid] != 0) ? 1.f : 0.f;
    __syncthreads();
    for (int o = 128; o > 0; o >>= 1) { if (tid < o) red[tid] += red[tid + o]; __syncthreads(); }
    if (tid == 0) d_llen[b] = red[0];
    __syncthreads();

    red[tid] = (tid < AN && aspect[b * AN + tid] != 0) ? 1.f : 0.f;
    __syncthreads();
    for (int o = 128; o > 0; o >>= 1) { if (tid < o) red[tid] += red[tid + o]; __syncthreads(); }
    if (tid == 0) { s_alen = red[0]; d_alen[b] = red[0]; }
    __syncthreads();
    float alen = s_alen;

    float part = 0.f;
    for (int d = tid; d < EN; d += 256) {
        float s = 0.f;
        #pragma unroll
        for (int a = 0; a < AN; a++) {
            int tok = aspect[b * AN + a];
            s += embed[(size_t)tok * EN + d];
        }
        s /= alen;
        d_asp[b * EN + d] = s;
        d_et[b * EN + d] = 0.f;
        part += s * aw[901 + d];
    }
    red[tid] = part;
    __syncthreads();
    for (int o = 128; o > 0; o >>= 1) { if (tid < o) red[tid] += red[tid + o]; __syncthreads(); }
    if (tid == 0) d_casp[b] = red[0];
}

__global__ void k_zero() {
    int i = blockIdx.x * 256 + threadIdx.x;
    if (i < 2 * 2 * 300 * 256) ((float*)d_hstate)[i] = 0.f;
    if (i < 4) { d_barcnt[i] = 0; d_bargen[i] = 0; }
}

// ---------------- vocab projection GEMM: P[v][n] = embed[v] . W_ih[n] + bias[n] ----------------
__global__ __launch_bounds__(256) void k_gemm_P(const float* __restrict__ embed,
                                                const float* __restrict__ fb,
                                                const float* __restrict__ bb) {
    int dir = blockIdx.z;
    const float* wT = d_wihT[dir];
    const float* bias = dir ? bb : fb;
    float* P = d_P[dir];

    __shared__ float As[8][128];
    __shared__ float Bs[8][128];
    int tid = threadIdx.x;
    int m0 = blockIdx.y * 128, n0 = blockIdx.x * 128;
    int tx = tid & 15, ty = tid >> 4;

    float acc[8][8];
    #pragma unroll
    for (int i = 0; i < 8; i++)
        #pragma unroll
        for (int j = 0; j < 8; j++) acc[i][j] = 0.f;

    int am = tid >> 1;
    int ak4 = (tid & 1) * 4;
    const float* aptr = embed + (size_t)(m0 + am) * 300;
    int bn = (tid & 31) * 4;
    int bk = tid >> 5;
    bool bnval = (n0 + bn + 3) < 1200;

    for (int k0 = 0; k0 < 304; k0 += 8) {
        float4 av = make_float4(0.f, 0.f, 0.f, 0.f);
        int ka = k0 + ak4;
        if (ka <= 296) av = *(const float4*)(aptr + ka);
        As[ak4 + 0][am] = av.x;
        As[ak4 + 1][am] = av.y;
        As[ak4 + 2][am] = av.z;
        As[ak4 + 3][am] = av.w;

        float4 bv = make_float4(0.f, 0.f, 0.f, 0.f);
        int kb = k0 + bk;
        if (kb < 300 && bnval) bv = *(const float4*)(wT + (size_t)kb * 1200 + n0 + bn);
        *(float4*)&Bs[bk][bn] = bv;
        __syncthreads();

        #pragma unroll
        for (int kk = 0; kk < 8; kk++) {
            float a[8], bf[8];
            *(float4*)(a)      = *(const float4*)&As[kk][ty * 8];
            *(float4*)(a + 4)  = *(const float4*)&As[kk][ty * 8 + 4];
            *(float4*)(bf)     = *(const float4*)&Bs[kk][tx * 8];
            *(float4*)(bf + 4) = *(const float4*)&Bs[kk][tx * 8 + 4];
            #pragma unroll
            for (int i = 0; i < 8; i++)
                #pragma unroll
                for (int j = 0; j < 8; j++) acc[i][j] += a[i] * bf[j];
        }
        __syncthreads();
    }

    // direct row-major store (n fastest); whole 8-col chunk is in or out (1200 % 8 == 0)
    int nb = n0 + tx * 8;
    if (nb + 7 < 1200) {
        float bv[8];
        #pragma unroll
        for (int j = 0; j < 8; j++) bv[j] = bias[nb + j];
        #pragma unroll
        for (int i = 0; i < 8; i++) {
            int m = m0 + ty * 8 + i;
            float* pr = P + (size_t)m * 1200 + nb;
            float4 lo = make_float4(acc[i][0] + bv[0], acc[i][1] + bv[1], acc[i][2] + bv[2], acc[i][3] + bv[3]);
            float4 hi = make_float4(acc[i][4] + bv[4], acc[i][5] + bv[5], acc[i][6] + bv[6], acc[i][7] + bv[7]);
            *(float4*)pr = lo;
            *(float4*)(pr + 4) = hi;
        }
    }
}

// ---------------- gather + transpose: Gpre[dir][t][n][b] = P[dir][text[b,t]][n] ----------------
// grid (SN, 2dir), 256 threads (8 warps). 8 b-rows per iteration, 32 iterations.
__global__ __launch_bounds__(256) void k_gather(const int* __restrict__ text) {
    int t = blockIdx.x;
    int dir = blockIdx.y;
    const float* P = d_P[dir];
    float* dst = d_Gpre + (size_t)dir * 65536 * 1200 + (size_t)t * 1200 * 256;

    __shared__ __align__(16) float tile[8][1204];
    int tid = threadIdx.x;
    int w = tid >> 5, lane = tid & 31;

    #pragma unroll 1
    for (int bi = 0; bi < 32; bi++) {
        int b = bi * 8 + w;
        int tok = text[b * SN + t];
        const float4* prow = (const float4*)(P + (size_t)tok * 1200);
        #pragma unroll
        for (int k = 0; k < 10; k++) {
            int k4 = lane + k * 32;
            if (k4 < 300) *(float4*)&tile[w][k4 * 4] = prow[k4];
        }
        __syncthreads();
        #pragma unroll 4
        for (int idx = tid; idx < 9600; idx += 256) {
            int n = idx >> 3, bb = idx & 7;
            dst[(size_t)n * 256 + bi * 8 + bb] = tile[bb][n];
        }
        __syncthreads();
    }
}

// ---------------- persistent LSTM: all 256 timesteps in one launch ----------------
// Grid = (30 ublocks, 2 bhalf, 2 dir) = 120 blocks, all resident (single wave).
// Barrier cohort = 30 u-blocks sharing (dir, bhalf). Cell state lives in registers.
__global__ __launch_bounds__(320) void k_steps_all() {
    int dir = blockIdx.z;
    int bh = blockIdx.y;
    int grp = dir * 2 + bh;
    int ub = blockIdx.x;
    int b0 = bh * 128;
    int tid = threadIdx.x;
    int cg = tid >> 5;   // warp = u-offset 0..9
    int bg = tid & 31;   // 4-batch group
    int u = ub * UB + cg;
    int b = b0 + bg * 4;

    extern __shared__ float smem[];
    float* Ws = smem;           // [300][40]
    float* Hs = smem + 12000;   // [2][KC][128]

    // stage pre-rearranged W tile once for all 256 steps
    {
        const float4* src = (const float4*)d_wstep[dir][ub];
        #pragma unroll
        for (int i = 0; i < 10; i++) {
            int idx = tid + i * 320;
            if (idx < 3000) ((float4*)Ws)[idx] = src[idx];
        }
    }

    // per-b location params, resident in registers
    float llv[4], alv[4], Mv[4];
    #pragma unroll
    for (int j = 0; j < 4; j++) {
        llv[j] = d_llen[b + j];
        alv[j] = d_alen[b + j];
        Mv[j]  = d_mlen[b + j];
    }

    float cc[4] = {0.f, 0.f, 0.f, 0.f};  // cell state: registers across all steps
    const float* gpre = d_Gpre + (size_t)dir * 65536 * 1200;
    unsigned gen = 0;

    #pragma unroll 1
    for (int st = 0; st < SN; st++) {
        int t = dir ? (SN - 1 - st) : st;
        const float* hprev = d_hstate[dir][st & 1];
        float* hnext = d_hstate[dir][(st + 1) & 1];

        float acc[4][4];  // [batch j][gate g]
        {
            const float* gp = gpre + (size_t)t * 1200 * 256;
            #pragma unroll
            for (int g = 0; g < 4; g++) {
                float4 v = *(const float4*)&gp[(size_t)(g * 300 + u) * 256 + b];
                acc[0][g] = v.x; acc[1][g] = v.y; acc[2][g] = v.z; acc[3][g] = v.w;
            }
        }

        // h chunk 0 -> shared
        #pragma unroll
        for (int i = 0; i < 3; i++) {
            int idx = tid + i * 320;
            if (idx < 960)
                *(float4*)&Hs[(idx >> 5) * 128 + (idx & 31) * 4] =
                    *(const float4*)&hprev[(idx >> 5) * 256 + b0 + (idx & 31) * 4];
        }
        __syncthreads();

        #pragma unroll 1
        for (int c = 0; c < 10; c++) {
            const float* hsc = Hs + (c & 1) * KC * 128;
            float4 pf[3];
            if (c < 9) {
                int kb = (c + 1) * KC;
                #pragma unroll
                for (int i = 0; i < 3; i++) {
                    int idx = tid + i * 320;
                    if (idx < 960)
                        pf[i] = *(const float4*)&hprev[(size_t)(kb + (idx >> 5)) * 256 + b0 + (idx & 31) * 4];
                }
            }
            const float* wbase = Ws + c * KC * 40 + cg * 4;
            #pragma unroll
            for (int kk = 0; kk < KC; kk++) {
                float4 hv = *(const float4*)&hsc[kk * 128 + bg * 4];
                float4 wv = *(const float4*)&wbase[kk * 40];
                acc[0][0] += hv.x * wv.x; acc[0][1] += hv.x * wv.y; acc[0][2] += hv.x * wv.z; acc[0][3] += hv.x * wv.w;
                acc[1][0] += hv.y * wv.x; acc[1][1] += hv.y * wv.y; acc[1][2] += hv.y * wv.z; acc[1][3] += hv.y * wv.w;
                acc[2][0] += hv.z * wv.x; acc[2][1] += hv.z * wv.y; acc[2][2] += hv.z * wv.z; acc[2][3] += hv.z * wv.w;
                acc[3][0] += hv.w * wv.x; acc[3][1] += hv.w * wv.y; acc[3][2] += hv.w * wv.z; acc[3][3] += hv.w * wv.w;
            }
            if (c < 9) {
                float* hsn = Hs + ((c + 1) & 1) * KC * 128;
                #pragma unroll
                for (int i = 0; i < 3; i++) {
                    int idx = tid + i * 320;
                    if (idx < 960)
                        *(float4*)&hsn[(idx >> 5) * 128 + (idx & 31) * 4] = pf[i];
                }
                __syncthreads();
            }
        }

        {
            float hh[4];
            float tt = (float)t;
            #pragma unroll
            for (int j = 0; j < 4; j++) {
                float ig = sigf(acc[j][0]);
                float fg = sigf(acc[j][1]);
                float gg = tanhf(acc[j][2]);
                float og = sigf(acc[j][3]);
                float c2 = fg * cc[j] + ig * gg;
                cc[j] = c2;
                hh[j] = og * tanhf(c2);
                float w;
                if (tt < llv[j]) w = 1.f - (llv[j] - tt) / Mv[j];
                else if (tt < llv[j] + alv[j]) w = 1.f;
                else if (tt < Mv[j]) w = 1.f - (tt - llv[j] - alv[j] + 1.f) / Mv[j];
                else w = 0.f;
                d_mem[((size_t)(b + j) * SN + t) * DN + dir * 300 + u] = hh[j] * w;
            }
            *(float4*)&hnext[u * 256 + b] = make_float4(hh[0], hh[1], hh[2], hh[3]);
        }

        // 30-block group barrier (skip after last step)
        if (st < SN - 1) {
            gen++;
            __syncthreads();
            if (tid == 0) {
                __threadfence();
                unsigned a = atomicAdd(&d_barcnt[grp], 1);
                if (a == NUB - 1) {
                    d_barcnt[grp] = 0;
                    __threadfence();
                    atomicAdd(&d_bargen[grp], 1);
                } else {
                    while (*(volatile unsigned*)&d_bargen[grp] < gen) { __nanosleep(40); }
                }
                __threadfence();
            }
            __syncthreads();
        }
    }
}

// ---------------- fill u column + gm = mem . attn_w[0:601]  ----------------
__global__ void k_gm(const float* __restrict__ aw) {
    int warp = threadIdx.x >> 5, lane = threadIdx.x & 31;
    int r = blockIdx.x * 8 + warp;
    int b = r >> 8, s = r & 255;
    float llv = d_llen[b], alv = d_alen[b], Mv = d_mlen[b];
    float ss = (float)s;
    float uu;
    if (ss < llv) uu = ss - llv;
    else if (ss < llv + alv) uu = 0.f;
    else if (ss < Mv) uu = ss - llv - alv + 1.f;
    else uu = 1.f;

    float* mrow = d_mem + (size_t)r * DN;
    float part = 0.f;
    for (int d = lane; d < DN; d += 32) {
        float v;
        if (d == 600) { v = uu; mrow[600] = uu; }
        else v = mrow[d];
        part += v * aw[d];
    }
    #pragma unroll
    for (int o = 16; o > 0; o >>= 1) part += __shfl_down_sync(0xffffffffu, part, o);
    if (lane == 0) d_gmT[s * BN + b] = part;
}

// ---------------- attention layer pieces ----------------
__global__ void k_gofs(const float* __restrict__ aw, const float* __restrict__ ab) {
    int b = blockIdx.x, tid = threadIdx.x;  // 128
    __shared__ float red[128];
    float p = 0.f;
    for (int k = tid; k < EN; k += 128) p += d_et[b * EN + k] * aw[601 + k];
    red[tid] = p;
    __syncthreads();
    for (int o = 64; o > 0; o >>= 1) { if (tid < o) red[tid] += red[tid + o]; __syncthreads(); }
    if (tid == 0) d_gofs[b] = red[0] + d_casp[b] + ab[0];
}

__global__ void k_softmax() {
    int s = blockIdx.x, b = threadIdx.x;
    __shared__ float red[256];
    float g = d_gmT[s * BN + b] + d_gofs[b];
    red[b] = g;
    __syncthreads();
    for (int o = 128; o > 0; o >>= 1) { if (b < o) red[b] = fmaxf(red[b], red[b + o]); __syncthreads(); }
    float mx = red[0];
    __syncthreads();
    float e = expf(g - mx);
    red[b] = e;
    __syncthreads();
    for (int o = 128; o > 0; o >>= 1) { if (b < o) red[b] += red[b + o]; __syncthreads(); }
    d_alphaT[s * BN + b] = e / red[0];
}

__global__ void k_isum() {
    int b = blockIdx.x, tid = threadIdx.x;  // 256
    __shared__ float al[256];
    al[tid] = d_alphaT[tid * BN + b];
    __syncthreads();
    float a0 = 0.f, a1 = 0.f, a2 = 0.f;
    int d0 = tid, d1 = tid + 256, d2 = tid + 512;
    bool v2 = d2 < DN;
    int d2c = v2 ? d2 : 600;
    const float* mb = d_mem + (size_t)b * SN * DN;
    #pragma unroll 4
    for (int s = 0; s < SN; s++) {
        float a = al[s];
        const float* mr = mb + (size_t)s * DN;
        a0 += a * mr[d0];
        a1 += a * mr[d1];
        a2 += a * mr[d2c];
    }
    d_ivec[b * DN + d0] = a0;
    d_ivec[b * DN + d1] = a1;
    if (v2) d_ivec[b * DN + d2] = a2;
}

// 4 batch elements per block: W rows loaded once, reused x4
__global__ __launch_bounds__(256) void k_gru(const float* __restrict__ bih,
                                             const float* __restrict__ bhh) {
    int b0 = blockIdx.x * 4;
    int tid = threadIdx.x;  // 256
    __shared__ float si[4][608];
    __shared__ float se[4][304];
    __shared__ float gi[4][904];
    __shared__ float gh[4][904];
    #pragma unroll
    for (int bb = 0; bb < 4; bb++) {
        for (int k = tid; k < DN; k += 256) si[bb][k] = d_ivec[(b0 + bb) * DN + k];
        for (int k = tid; k < EN; k += 256) se[bb][k] = d_et[(b0 + bb) * EN + k];
    }
    __syncthreads();

    int r0 = tid, r1 = tid + 256, r2 = tid + 512, r3 = tid + 768;
    bool v3 = r3 < 900;
    int r3c = v3 ? r3 : 899;

    float acc[4][4];
    #pragma unroll
    for (int bb = 0; bb < 4; bb++) {
        acc[bb][0] = bih[r0]; acc[bb][1] = bih[r1]; acc[bb][2] = bih[r2]; acc[bb][3] = bih[r3c];
    }
    for (int k = 0; k < DN; k++) {
        const float* w = d_gwihT + (size_t)k * 900;
        float w0 = w[r0], w1 = w[r1], w2 = w[r2], w3 = w[r3c];
        #pragma unroll
        for (int bb = 0; bb < 4; bb++) {
            float v = si[bb][k];
            acc[bb][0] += v * w0; acc[bb][1] += v * w1; acc[bb][2] += v * w2; acc[bb][3] += v * w3;
        }
    }
    #pragma unroll
    for (int bb = 0; bb < 4; bb++) {
        gi[bb][r0] = acc[bb][0]; gi[bb][r1] = acc[bb][1]; gi[bb][r2] = acc[bb][2];
        if (v3) gi[bb][r3] = acc[bb][3];
    }

    #pragma unroll
    for (int bb = 0; bb < 4; bb++) {
        acc[bb][0] = bhh[r0]; acc[bb][1] = bhh[r1]; acc[bb][2] = bhh[r2]; acc[bb][3] = bhh[r3c];
    }
    for (int k = 0; k < EN; k++) {
        const float* w = d_gwhhT + (size_t)k * 900;
        float w0 = w[r0], w1 = w[r1], w2 = w[r2], w3 = w[r3c];
        #pragma unroll
        for (int bb = 0; bb < 4; bb++) {
            float v = se[bb][k];
            acc[bb][0] += v * w0; acc[bb][1] += v * w1; acc[bb][2] += v * w2; acc[bb][3] += v * w3;
        }
    }
    #pragma unroll
    for (int bb = 0; bb < 4; bb++) {
        gh[bb][r0] = acc[bb][0]; gh[bb][r1] = acc[bb][1]; gh[bb][r2] = acc[bb][2];
        if (v3) gh[bb][r3] = acc[bb][3];
    }
    __syncthreads();

    for (int e = tid; e < EN; e += 256) {
        #pragma unroll
        for (int bb = 0; bb < 4; bb++) {
            float rr = sigf(gi[bb][e] + gh[bb][e]);
            float zz = sigf(gi[bb][300 + e] + gh[bb][300 + e]);
            float nn = tanhf(gi[bb][600 + e] + rr * gh[bb][600 + e]);
            d_et[(b0 + bb) * EN + e] = (1.f - zz) * nn + zz * se[bb][e];
        }
    }
}

__global__ void k_dense(const float* __restrict__ dw, const float* __restrict__ db,
                        float* __restrict__ out) {
    int b = blockIdx.x;
    int p = threadIdx.x >> 5;
    int lane = threadIdx.x & 31;
    if (p < POLN) {
        float s = 0.f;
        for (int k = lane; k < EN; k += 32) s += d_et[b * EN + k] * dw[p * EN + k];
        #pragma unroll
        for (int o = 16; o > 0; o >>= 1) s += __shfl_down_sync(0xffffffffu, s, o);
        if (lane == 0) out[b * POLN + p] = s + db[p];
    }
}

// ---------------- launcher ----------------
extern "C" void kernel_launch(void* const* d_in, const int* in_sizes, int n_in,
                              void* d_out, int out_size) {
    const int* text = (const int*)d_in[0];
    const int* aspect = (const int*)d_in[1];
    const int* left = (const int*)d_in[2];
    const float* embed = (const float*)d_in[3];
    const float* fwih = (const float*)d_in[4];
    const float* fwhh = (const float*)d_in[5];
    const float* fb = (const float*)d_in[6];
    const float* bwih = (const float*)d_in[7];
    const float* bwhh = (const float*)d_in[8];
    const float* bb = (const float*)d_in[9];
    const float* aw = (const float*)d_in[10];
    const float* ab = (const float*)d_in[11];
    const float* gwih = (const float*)d_in[12];
    const float* gwhh = (const float*)d_in[13];
    const float* gbih = (const float*)d_in[14];
    const float* gbhh = (const float*)d_in[15];
    const float* dw = (const float*)d_in[16];
    const float* db = (const float*)d_in[17];
    float* out = (float*)d_out;

    const int step_smem = (12000 + 2 * KC * 128) * 4;  // 78720 B
    cudaFuncSetAttribute(k_steps_all, cudaFuncAttributeMaxDynamicSharedMemorySize, step_smem);

    k_transpose_all<<<dim3(19, 38, 6), dim3(32, 8)>>>(fwih, fwhh, bwih, bwhh, gwih, gwhh);
    k_wstep<<<dim3(NUB, 2), 256>>>();
    k_prep_b<<<256, 256>>>(text, left, aspect, embed, aw);
    k_zero<<<1200, 256>>>();
    k_gemm_P<<<dim3(10, VN / 128, 2), 256>>>(embed, fb, bb);
    k_gather<<<dim3(SN, 2), 256>>>(text);
    k_steps_all<<<dim3(NUB, 2, 2), 320, step_smem>>>();
    k_gm<<<8192, 256>>>(aw);
    for (int l = 0; l < 4; l++) {
        k_gofs<<<256, 128>>>(aw, ab);
        k_softmax<<<256, 256>>>();
        k_isum<<<256, 256>>>();
        k_gru<<<64, 256>>>(gbih, gbhh);
    }
    k_dense<<<256, 96>>>(dw, db, out);
}

// round 11
// speedup vs baseline: 1.6168x; 1.0098x over previous
#include <cuda_runtime.h>
#include <math.h>

#define BN 256
#define SN 256
#define EN 300
#define HN 300
#define G4 1200
#define DN 601
#define AN 16
#define POLN 3
#define KC 30
#define UB 10     // u-units per step block
#define NUB 30    // number of u-blocks (30*10 = 300)
#define VN 32000

typedef unsigned long long ull;

// packed f32x2 helpers (Blackwell): each lane is an exact fp32 FMA
__device__ __forceinline__ ull pk2(float lo, float hi) {
    ull r; asm("mov.b64 %0, {%1,%2};" : "=l"(r) : "f"(lo), "f"(hi)); return r;
}
__device__ __forceinline__ void up2(ull v, float& lo, float& hi) {
    asm("mov.b64 {%0,%1}, %2;" : "=f"(lo), "=f"(hi) : "l"(v));
}
__device__ __forceinline__ void fma2(ull& c, ull a, ull b) {
    asm("fma.rn.f32x2 %0, %1, %2, %3;" : "=l"(c) : "l"(a), "l"(b), "l"(c));
}

// ---------------- static device scratch (no allocations allowed) ----------------
__device__ float d_wihT[2][300 * 1200];      // input weights, k-major
__device__ float d_whhT[2][300 * 1200];      // recurrent weights, k-major
__device__ float d_wstep[2][NUB][300 * 40];  // step weights: [dir][ub][k][uoff*4+g]
__device__ float d_P[2][VN * 1200];          // vocab projection: embed@W_ih^T + bias
__device__ float d_gwihT[601 * 900];         // GRU W_ih^T  (k-major)
__device__ float d_gwhhT[300 * 900];         // GRU W_hh^T  (k-major)
__device__ float d_Gpre[2 * 65536 * 1200];   // input gates, layout [dir][t][n][b]
__device__ float d_mem[65536 * 601];         // location-weighted memory [b][s][d]
__device__ float d_hstate[2][2][300 * 256];  // [dir][parity][u][b]
__device__ float d_gmT[65536];               // [s][b]
__device__ float d_alphaT[65536];            // [s][b]
__device__ float d_gofs[256];
__device__ float d_asp[256 * 300];
__device__ float d_casp[256];
__device__ float d_et[256 * 300];
__device__ float d_ivec[256 * 601];
__device__ float d_llen[256], d_alen[256], d_mlen[256];
__device__ unsigned d_barcnt[4];
__device__ unsigned d_bargen[4];

__device__ __forceinline__ float sigf(float x) { return 1.f / (1.f + expf(-x)); }

// ---------------- weight transposes ----------------
__global__ void k_transpose_all(const float* __restrict__ fwih, const float* __restrict__ fwhh,
                                const float* __restrict__ bwih, const float* __restrict__ bwhh,
                                const float* __restrict__ gwih, const float* __restrict__ gwhh) {
    int id = blockIdx.z;
    const float* src;
    float* dst;
    int R, C;
    switch (id) {
        case 0: src = fwih; dst = d_wihT[0]; R = 1200; C = 300; break;
        case 1: src = fwhh; dst = d_whhT[0]; R = 1200; C = 300; break;
        case 2: src = bwih; dst = d_wihT[1]; R = 1200; C = 300; break;
        case 3: src = bwhh; dst = d_whhT[1]; R = 1200; C = 300; break;
        case 4: src = gwih; dst = d_gwihT;   R = 900;  C = 601; break;
        default: src = gwhh; dst = d_gwhhT;  R = 900;  C = 300; break;
    }
    __shared__ float tile[32][33];
    int c0 = blockIdx.x * 32, r0 = blockIdx.y * 32;
    int x = threadIdx.x, y = threadIdx.y;  // 32 x 8
    #pragma unroll
    for (int i = 0; i < 32; i += 8) {
        int r = r0 + y + i, c = c0 + x;
        if (r < R && c < C) tile[y + i][x] = src[(size_t)r * C + c];
    }
    __syncthreads();
    #pragma unroll
    for (int i = 0; i < 32; i += 8) {
        int c = c0 + y + i, r = r0 + x;
        if (c < C && r < R) dst[(size_t)c * R + r] = tile[x][y + i];
    }
}

// build d_wstep from d_whhT (one block per (dir, ub))
__global__ void k_wstep() {
    int dir = blockIdx.y;
    int ub = blockIdx.x;
    const float* w = d_whhT[dir];
    float* dst = d_wstep[dir][ub];
    for (int i = threadIdx.x; i < 300 * 40; i += blockDim.x) {
        int k = i / 40;
        int col = i % 40;
        int uoff = col >> 2, g = col & 3;
        dst[i] = w[(size_t)k * 1200 + g * 300 + ub * UB + uoff];
    }
}

// ---------------- lengths / aspect vector / init ----------------
__global__ void k_prep_b(const int* __restrict__ text, const int* __restrict__ left,
                         const int* __restrict__ aspect, const float* __restrict__ embed,
                         const float* __restrict__ aw) {
    int b = blockIdx.x;
    int tid = threadIdx.x;  // 256
    __shared__ float red[256];
    __shared__ float s_alen;

    red[tid] = (text[b * SN + tid] != 0) ? 1.f : 0.f;
    __syncthreads();
    for (int o = 128; o > 0; o >>= 1) { if (tid < o) red[tid] += red[tid + o]; __syncthreads(); }
    if (tid == 0) d_mlen[b] = red[0];
    __syncthreads();

    red[tid] = (left[b * SN + tid] != 0) ? 1.f : 0.f;
    __syncthreads();
    for (int o = 128; o > 0; o >>= 1) { if (tid < o) red[tid] += red[tid + o]; __syncthreads(); }
    if (tid == 0) d_llen[b] = red[0];
    __syncthreads();

    red[tid] = (tid < AN && aspect[b * AN + tid] != 0) ? 1.f : 0.f;
    __syncthreads();
    for (int o = 128; o > 0; o >>= 1) { if (tid < o) red[tid] += red[tid + o]; __syncthreads(); }
    if (tid == 0) { s_alen = red[0]; d_alen[b] = red[0]; }
    __syncthreads();
    float alen = s_alen;

    float part = 0.f;
    for (int d = tid; d < EN; d += 256) {
        float s = 0.f;
        #pragma unroll
        for (int a = 0; a < AN; a++) {
            int tok = aspect[b * AN + a];
            s += embed[(size_t)tok * EN + d];
        }
        s /= alen;
        d_asp[b * EN + d] = s;
        d_et[b * EN + d] = 0.f;
        part += s * aw[901 + d];
    }
    red[tid] = part;
    __syncthreads();
    for (int o = 128; o > 0; o >>= 1) { if (tid < o) red[tid] += red[tid + o]; __syncthreads(); }
    if (tid == 0) d_casp[b] = red[0];
}

__global__ void k_zero() {
    int i = blockIdx.x * 256 + threadIdx.x;
    if (i < 2 * 2 * 300 * 256) ((float*)d_hstate)[i] = 0.f;
    if (i < 4) { d_barcnt[i] = 0; d_bargen[i] = 0; }
}

// ---------------- vocab projection GEMM: P[v][n] = embed[v] . W_ih[n] + bias[n] ----------------
__global__ __launch_bounds__(256) void k_gemm_P(const float* __restrict__ embed,
                                                const float* __restrict__ fb,
                                                const float* __restrict__ bb) {
    int dir = blockIdx.z;
    const float* wT = d_wihT[dir];
    const float* bias = dir ? bb : fb;
    float* P = d_P[dir];

    __shared__ float As[8][128];
    __shared__ float Bs[8][128];
    int tid = threadIdx.x;
    int m0 = blockIdx.y * 128, n0 = blockIdx.x * 128;
    int tx = tid & 15, ty = tid >> 4;

    ull acc2[8][4];  // [i][ jpair ] : (j0,j1),(j2,j3),(j4,j5),(j6,j7)
    ull z2 = pk2(0.f, 0.f);
    #pragma unroll
    for (int i = 0; i < 8; i++)
        #pragma unroll
        for (int p = 0; p < 4; p++) acc2[i][p] = z2;

    int am = tid >> 1;
    int ak4 = (tid & 1) * 4;
    const float* aptr = embed + (size_t)(m0 + am) * 300;
    int bn = (tid & 31) * 4;
    int bk = tid >> 5;
    bool bnval = (n0 + bn + 3) < 1200;

    for (int k0 = 0; k0 < 304; k0 += 8) {
        float4 av = make_float4(0.f, 0.f, 0.f, 0.f);
        int ka = k0 + ak4;
        if (ka <= 296) av = *(const float4*)(aptr + ka);
        As[ak4 + 0][am] = av.x;
        As[ak4 + 1][am] = av.y;
        As[ak4 + 2][am] = av.z;
        As[ak4 + 3][am] = av.w;

        float4 bv = make_float4(0.f, 0.f, 0.f, 0.f);
        int kb = k0 + bk;
        if (kb < 300 && bnval) bv = *(const float4*)(wT + (size_t)kb * 1200 + n0 + bn);
        *(float4*)&Bs[bk][bn] = bv;
        __syncthreads();

        #pragma unroll
        for (int kk = 0; kk < 8; kk++) {
            float a[8], bf[8];
            *(float4*)(a)      = *(const float4*)&As[kk][ty * 8];
            *(float4*)(a + 4)  = *(const float4*)&As[kk][ty * 8 + 4];
            *(float4*)(bf)     = *(const float4*)&Bs[kk][tx * 8];
            *(float4*)(bf + 4) = *(const float4*)&Bs[kk][tx * 8 + 4];
            ull bp[4];
            #pragma unroll
            for (int p = 0; p < 4; p++) bp[p] = pk2(bf[2 * p], bf[2 * p + 1]);
            #pragma unroll
            for (int i = 0; i < 8; i++) {
                ull ai = pk2(a[i], a[i]);
                #pragma unroll
                for (int p = 0; p < 4; p++) fma2(acc2[i][p], ai, bp[p]);
            }
        }
        __syncthreads();
    }

    // direct row-major store (n fastest); whole 8-col chunk is in or out (1200 % 8 == 0)
    int nb = n0 + tx * 8;
    if (nb + 7 < 1200) {
        float bv[8];
        #pragma unroll
        for (int j = 0; j < 8; j++) bv[j] = bias[nb + j];
        #pragma unroll
        for (int i = 0; i < 8; i++) {
            float ac[8];
            #pragma unroll
            for (int p = 0; p < 4; p++) up2(acc2[i][p], ac[2 * p], ac[2 * p + 1]);
            int m = m0 + ty * 8 + i;
            float* pr = P + (size_t)m * 1200 + nb;
            float4 lo = make_float4(ac[0] + bv[0], ac[1] + bv[1], ac[2] + bv[2], ac[3] + bv[3]);
            float4 hi = make_float4(ac[4] + bv[4], ac[5] + bv[5], ac[6] + bv[6], ac[7] + bv[7]);
            *(float4*)pr = lo;
            *(float4*)(pr + 4) = hi;
        }
    }
}

// ---------------- gather + transpose: Gpre[dir][t][n][b] = P[dir][text[b,t]][n] ----------------
__global__ __launch_bounds__(256) void k_gather(const int* __restrict__ text) {
    int t = blockIdx.x;
    int dir = blockIdx.y;
    const float* P = d_P[dir];
    float* dst = d_Gpre + (size_t)dir * 65536 * 1200 + (size_t)t * 1200 * 256;

    __shared__ __align__(16) float tile[8][1204];
    int tid = threadIdx.x;
    int w = tid >> 5, lane = tid & 31;

    #pragma unroll 1
    for (int bi = 0; bi < 32; bi++) {
        int b = bi * 8 + w;
        int tok = text[b * SN + t];
        const float4* prow = (const float4*)(P + (size_t)tok * 1200);
        #pragma unroll
        for (int k = 0; k < 10; k++) {
            int k4 = lane + k * 32;
            if (k4 < 300) *(float4*)&tile[w][k4 * 4] = prow[k4];
        }
        __syncthreads();
        #pragma unroll 4
        for (int idx = tid; idx < 9600; idx += 256) {
            int n = idx >> 3, bb = idx & 7;
            dst[(size_t)n * 256 + bi * 8 + bb] = tile[bb][n];
        }
        __syncthreads();
    }
}

// ---------------- persistent LSTM: all 256 timesteps in one launch ----------------
__global__ __launch_bounds__(320) void k_steps_all() {
    int dir = blockIdx.z;
    int bh = blockIdx.y;
    int grp = dir * 2 + bh;
    int ub = blockIdx.x;
    int b0 = bh * 128;
    int tid = threadIdx.x;
    int cg = tid >> 5;   // warp = u-offset 0..9
    int bg = tid & 31;   // 4-batch group
    int u = ub * UB + cg;
    int b = b0 + bg * 4;

    extern __shared__ float smem[];
    float* Ws = smem;           // [300][40]
    float* Hs = smem + 12000;   // [2][KC][128]

    // stage pre-rearranged W tile once for all 256 steps
    {
        const float4* src = (const float4*)d_wstep[dir][ub];
        #pragma unroll
        for (int i = 0; i < 10; i++) {
            int idx = tid + i * 320;
            if (idx < 3000) ((float4*)Ws)[idx] = src[idx];
        }
    }

    // per-b location params, resident in registers
    float llv[4], alv[4], Mv[4];
    #pragma unroll
    for (int j = 0; j < 4; j++) {
        llv[j] = d_llen[b + j];
        alv[j] = d_alen[b + j];
        Mv[j]  = d_mlen[b + j];
    }

    float cc[4] = {0.f, 0.f, 0.f, 0.f};  // cell state: registers across all steps
    const float* gpre = d_Gpre + (size_t)dir * 65536 * 1200;
    unsigned gen = 0;

    #pragma unroll 1
    for (int st = 0; st < SN; st++) {
        int t = dir ? (SN - 1 - st) : st;
        const float* hprev = d_hstate[dir][st & 1];
        float* hnext = d_hstate[dir][(st + 1) & 1];

        // acc pairs: [j][0]=(gate_i,gate_f), [j][1]=(gate_g,gate_o)
        ull acc2[4][2];
        {
            const float* gp = gpre + (size_t)t * 1200 * 256;
            float4 vg[4];
            #pragma unroll
            for (int g = 0; g < 4; g++)
                vg[g] = *(const float4*)&gp[(size_t)(g * 300 + u) * 256 + b];
            acc2[0][0] = pk2(vg[0].x, vg[1].x); acc2[0][1] = pk2(vg[2].x, vg[3].x);
            acc2[1][0] = pk2(vg[0].y, vg[1].y); acc2[1][1] = pk2(vg[2].y, vg[3].y);
            acc2[2][0] = pk2(vg[0].z, vg[1].z); acc2[2][1] = pk2(vg[2].z, vg[3].z);
            acc2[3][0] = pk2(vg[0].w, vg[1].w); acc2[3][1] = pk2(vg[2].w, vg[3].w);
        }

        // h chunk 0 -> shared
        #pragma unroll
        for (int i = 0; i < 3; i++) {
            int idx = tid + i * 320;
            if (idx < 960)
                *(float4*)&Hs[(idx >> 5) * 128 + (idx & 31) * 4] =
                    *(const float4*)&hprev[(idx >> 5) * 256 + b0 + (idx & 31) * 4];
        }
        __syncthreads();

        #pragma unroll 1
        for (int c = 0; c < 10; c++) {
            const float* hsc = Hs + (c & 1) * KC * 128;
            float4 pf[3];
            if (c < 9) {
                int kb = (c + 1) * KC;
                #pragma unroll
                for (int i = 0; i < 3; i++) {
                    int idx = tid + i * 320;
                    if (idx < 960)
                        pf[i] = *(const float4*)&hprev[(size_t)(kb + (idx >> 5)) * 256 + b0 + (idx & 31) * 4];
                }
            }
            const float* wbase = Ws + c * KC * 40 + cg * 4;
            #pragma unroll
            for (int kk = 0; kk < KC; kk++) {
                float4 hv = *(const float4*)&hsc[kk * 128 + bg * 4];
                float4 wv = *(const float4*)&wbase[kk * 40];
                ull w01 = pk2(wv.x, wv.y);
                ull w23 = pk2(wv.z, wv.w);
                ull h0 = pk2(hv.x, hv.x);
                fma2(acc2[0][0], h0, w01); fma2(acc2[0][1], h0, w23);
                ull h1 = pk2(hv.y, hv.y);
                fma2(acc2[1][0], h1, w01); fma2(acc2[1][1], h1, w23);
                ull h2 = pk2(hv.z, hv.z);
                fma2(acc2[2][0], h2, w01); fma2(acc2[2][1], h2, w23);
                ull h3 = pk2(hv.w, hv.w);
                fma2(acc2[3][0], h3, w01); fma2(acc2[3][1], h3, w23);
            }
            if (c < 9) {
                float* hsn = Hs + ((c + 1) & 1) * KC * 128;
                #pragma unroll
                for (int i = 0; i < 3; i++) {
                    int idx = tid + i * 320;
                    if (idx < 960)
                        *(float4*)&hsn[(idx >> 5) * 128 + (idx & 31) * 4] = pf[i];
                }
                __syncthreads();
            }
        }

        {
            float hh[4];
            float tt = (float)t;
            #pragma unroll
            for (int j = 0; j < 4; j++) {
                float gi, gf, gg0, go;
                up2(acc2[j][0], gi, gf);
                up2(acc2[j][1], gg0, go);
                float ig = sigf(gi);
                float fg = sigf(gf);
                float gg = tanhf(gg0);
                float og = sigf(go);
                float c2 = fg * cc[j] + ig * gg;
                cc[j] = c2;
                hh[j] = og * tanhf(c2);
                float w;
                if (tt < llv[j]) w = 1.f - (llv[j] - tt) / Mv[j];
                else if (tt < llv[j] + alv[j]) w = 1.f;
                else if (tt < Mv[j]) w = 1.f - (tt - llv[j] - alv[j] + 1.f) / Mv[j];
                else w = 0.f;
                d_mem[((size_t)(b + j) * SN + t) * DN + dir * 300 + u] = hh[j] * w;
            }
            *(float4*)&hnext[u * 256 + b] = make_float4(hh[0], hh[1], hh[2], hh[3]);
        }

        // 30-block group barrier (skip after last step)
        if (st < SN - 1) {
            gen++;
            __syncthreads();
            if (tid == 0) {
                __threadfence();
                unsigned a = atomicAdd(&d_barcnt[grp], 1);
                if (a == NUB - 1) {
                    d_barcnt[grp] = 0;
                    __threadfence();
                    atomicAdd(&d_bargen[grp], 1);
                } else {
                    while (*(volatile unsigned*)&d_bargen[grp] < gen) { __nanosleep(40); }
                }
                __threadfence();
            }
            __syncthreads();
        }
    }
}

// ---------------- fill u column + gm = mem . attn_w[0:601]  ----------------
__global__ void k_gm(const float* __restrict__ aw) {
    int warp = threadIdx.x >> 5, lane = threadIdx.x & 31;
    int r = blockIdx.x * 8 + warp;
    int b = r >> 8, s = r & 255;
    float llv = d_llen[b], alv = d_alen[b], Mv = d_mlen[b];
    float ss = (float)s;
    float uu;
    if (ss < llv) uu = ss - llv;
    else if (ss < llv + alv) uu = 0.f;
    else if (ss < Mv) uu = ss - llv - alv + 1.f;
    else uu = 1.f;

    float* mrow = d_mem + (size_t)r * DN;
    float part = 0.f;
    for (int d = lane; d < DN; d += 32) {
        float v;
        if (d == 600) { v = uu; mrow[600] = uu; }
        else v = mrow[d];
        part += v * aw[d];
    }
    #pragma unroll
    for (int o = 16; o > 0; o >>= 1) part += __shfl_down_sync(0xffffffffu, part, o);
    if (lane == 0) d_gmT[s * BN + b] = part;
}

// ---------------- attention layer pieces ----------------
__global__ void k_gofs(const float* __restrict__ aw, const float* __restrict__ ab) {
    int b = blockIdx.x, tid = threadIdx.x;  // 128
    __shared__ float red[128];
    float p = 0.f;
    for (int k = tid; k < EN; k += 128) p += d_et[b * EN + k] * aw[601 + k];
    red[tid] = p;
    __syncthreads();
    for (int o = 64; o > 0; o >>= 1) { if (tid < o) red[tid] += red[tid + o]; __syncthreads(); }
    if (tid == 0) d_gofs[b] = red[0] + d_casp[b] + ab[0];
}

__global__ void k_softmax() {
    int s = blockIdx.x, b = threadIdx.x;
    __shared__ float red[256];
    float g = d_gmT[s * BN + b] + d_gofs[b];
    red[b] = g;
    __syncthreads();
    for (int o = 128; o > 0; o >>= 1) { if (b < o) red[b] = fmaxf(red[b], red[b + o]); __syncthreads(); }
    float mx = red[0];
    __syncthreads();
    float e = expf(g - mx);
    red[b] = e;
    __syncthreads();
    for (int o = 128; o > 0; o >>= 1) { if (b < o) red[b] += red[b + o]; __syncthreads(); }
    d_alphaT[s * BN + b] = e / red[0];
}

__global__ void k_isum() {
    int b = blockIdx.x, tid = threadIdx.x;  // 256
    __shared__ float al[256];
    al[tid] = d_alphaT[tid * BN + b];
    __syncthreads();
    float a0 = 0.f, a1 = 0.f, a2 = 0.f;
    int d0 = tid, d1 = tid + 256, d2 = tid + 512;
    bool v2 = d2 < DN;
    int d2c = v2 ? d2 : 600;
    const float* mb = d_mem + (size_t)b * SN * DN;
    #pragma unroll 4
    for (int s = 0; s < SN; s++) {
        float a = al[s];
        const float* mr = mb + (size_t)s * DN;
        a0 += a * mr[d0];
        a1 += a * mr[d1];
        a2 += a * mr[d2c];
    }
    d_ivec[b * DN + d0] = a0;
    d_ivec[b * DN + d1] = a1;
    if (v2) d_ivec[b * DN + d2] = a2;
}

// 4 batch elements per block: W rows loaded once, reused x4
__global__ __launch_bounds__(256) void k_gru(const float* __restrict__ bih,
                                             const float* __restrict__ bhh) {
    int b0 = blockIdx.x * 4;
    int tid = threadIdx.x;  // 256
    __shared__ float si[4][608];
    __shared__ float se[4][304];
    __shared__ float gi[4][904];
    __shared__ float gh[4][904];
    #pragma unroll
    for (int bb = 0; bb < 4; bb++) {
        for (int k = tid; k < DN; k += 256) si[bb][k] = d_ivec[(b0 + bb) * DN + k];
        for (int k = tid; k < EN; k += 256) se[bb][k] = d_et[(b0 + bb) * EN + k];
    }
    __syncthreads();

    int r0 = tid, r1 = tid + 256, r2 = tid + 512, r3 = tid + 768;
    bool v3 = r3 < 900;
    int r3c = v3 ? r3 : 899;

    float acc[4][4];
    #pragma unroll
    for (int bb = 0; bb < 4; bb++) {
        acc[bb][0] = bih[r0]; acc[bb][1] = bih[r1]; acc[bb][2] = bih[r2]; acc[bb][3] = bih[r3c];
    }
    for (int k = 0; k < DN; k++) {
        const float* w = d_gwihT + (size_t)k * 900;
        float w0 = w[r0], w1 = w[r1], w2 = w[r2], w3 = w[r3c];
        #pragma unroll
        for (int bb = 0; bb < 4; bb++) {
            float v = si[bb][k];
            acc[bb][0] += v * w0; acc[bb][1] += v * w1; acc[bb][2] += v * w2; acc[bb][3] += v * w3;
        }
    }
    #pragma unroll
    for (int bb = 0; bb < 4; bb++) {
        gi[bb][r0] = acc[bb][0]; gi[bb][r1] = acc[bb][1]; gi[bb][r2] = acc[bb][2];
        if (v3) gi[bb][r3] = acc[bb][3];
    }

    #pragma unroll
    for (int bb = 0; bb < 4; bb++) {
        acc[bb][0] = bhh[r0]; acc[bb][1] = bhh[r1]; acc[bb][2] = bhh[r2]; acc[bb][3] = bhh[r3c];
    }
    for (int k = 0; k < EN; k++) {
        const float* w = d_gwhhT + (size_t)k * 900;
        float w0 = w[r0], w1 = w[r1], w2 = w[r2], w3 = w[r3c];
        #pragma unroll
        for (int bb = 0; bb < 4; bb++) {
            float v = se[bb][k];
            acc[bb][0] += v * w0; acc[bb][1] += v * w1; acc[bb][2] += v * w2; acc[bb][3] += v * w3;
        }
    }
    #pragma unroll
    for (int bb = 0; bb < 4; bb++) {
        gh[bb][r0] = acc[bb][0]; gh[bb][r1] = acc[bb][1]; gh[bb][r2] = acc[bb][2];
        if (v3) gh[bb][r3] = acc[bb][3];
    }
    __syncthreads();

    for (int e = tid; e < EN; e += 256) {
        #pragma unroll
        for (int bb = 0; bb < 4; bb++) {
            float rr = sigf(gi[bb][e] + gh[bb][e]);
            float zz = sigf(gi[bb][300 + e] + gh[bb][300 + e]);
            float nn = tanhf(gi[bb][600 + e] + rr * gh[bb][600 + e]);
            d_et[(b0 + bb) * EN + e] = (1.f - zz) * nn + zz * se[bb][e];
        }
    }
}

__global__ void k_dense(const float* __restrict__ dw, const float* __restrict__ db,
                        float* __restrict__ out) {
    int b = blockIdx.x;
    int p = threadIdx.x >> 5;
    int lane = threadIdx.x & 31;
    if (p < POLN) {
        float s = 0.f;
        for (int k = lane; k < EN; k += 32) s += d_et[b * EN + k] * dw[p * EN + k];
        #pragma unroll
        for (int o = 16; o > 0; o >>= 1) s += __shfl_down_sync(0xffffffffu, s, o);
        if (lane == 0) out[b * POLN + p] = s + db[p];
    }
}

// ---------------- launcher ----------------
extern "C" void kernel_launch(void* const* d_in, const int* in_sizes, int n_in,
                              void* d_out, int out_size) {
    const int* text = (const int*)d_in[0];
    const int* aspect = (const int*)d_in[1];
    const int* left = (const int*)d_in[2];
    const float* embed = (const float*)d_in[3];
    const float* fwih = (const float*)d_in[4];
    const float* fwhh = (const float*)d_in[5];
    const float* fb = (const float*)d_in[6];
    const float* bwih = (const float*)d_in[7];
    const float* bwhh = (const float*)d_in[8];
    const float* bb = (const float*)d_in[9];
    const float* aw = (const float*)d_in[10];
    const float* ab = (const float*)d_in[11];
    const float* gwih = (const float*)d_in[12];
    const float* gwhh = (const float*)d_in[13];
    const float* gbih = (const float*)d_in[14];
    const float* gbhh = (const float*)d_in[15];
    const float* dw = (const float*)d_in[16];
    const float* db = (const float*)d_in[17];
    float* out = (float*)d_out;

    const int step_smem = (12000 + 2 * KC * 128) * 4;  // 78720 B
    cudaFuncSetAttribute(k_steps_all, cudaFuncAttributeMaxDynamicSharedMemorySize, step_smem);

    k_transpose_all<<<dim3(19, 38, 6), dim3(32, 8)>>>(fwih, fwhh, bwih, bwhh, gwih, gwhh);
    k_wstep<<<dim3(NUB, 2), 256>>>();
    k_prep_b<<<256, 256>>>(text, left, aspect, embed, aw);
    k_zero<<<1200, 256>>>();
    k_gemm_P<<<dim3(10, VN / 128, 2), 256>>>(embed, fb, bb);
    k_gather<<<dim3(SN, 2), 256>>>(text);
    k_steps_all<<<dim3(NUB, 2, 2), 320, step_smem>>>();
    k_gm<<<8192, 256>>>(aw);
    for (int l = 0; l < 4; l++) {
        k_gofs<<<256, 128>>>(aw, ab);
        k_softmax<<<256, 256>>>();
        k_isum<<<256, 256>>>();
        k_gru<<<64, 256>>>(gbih, gbhh);
    }
    k_dense<<<256, 96>>>(dw, db, out);
}